// round 3
// baseline (speedup 1.0000x reference)
#include <cuda_runtime.h>
#include <math.h>

#define NBL   4096          // B*L
#define HHH   16            // heads
#define HIDD  1024
#define OUTC  128           // 2*D hidden layer width
#define KEXT  268           // 256 branch rows + 12 stat rows
#define KCH   67            // KEXT/4
#define XPAD  272           // padded per-head x row (multiple of 4)

typedef unsigned long long ull;

// scratch (device globals: allocation-free rule)
__device__ __align__(16) float g_Hc[NBL * OUTC];   // hidden @ W1[0:1024] + b1
__device__ __align__(16) float g_SW[12 * OUTC];    // stat-row column sums

// ---------- packed f32x2 helpers ----------
__device__ __forceinline__ ull pack2(float a, float b) {
    ull r;
    asm("mov.b64 %0, {%1, %2};" : "=l"(r)
        : "r"(__float_as_uint(a)), "r"(__float_as_uint(b)));
    return r;
}
__device__ __forceinline__ ull fma2(ull a, ull b, ull c) {
    ull d;
    asm("fma.rn.f32x2 %0, %1, %2, %3;" : "=l"(d) : "l"(a), "l"(b), "l"(c));
    return d;
}
__device__ __forceinline__ float2 unp2(ull a) {
    unsigned lo, hi;
    asm("mov.b64 {%0, %1}, %2;" : "=r"(lo), "=r"(hi) : "l"(a));
    return make_float2(__uint_as_float(lo), __uint_as_float(hi));
}
__device__ __forceinline__ float gelu_f(float x) {
    return 0.5f * x * (1.0f + erff(x * 0.70710678118654752440f));
}

// ---------------------------------------------------------------------------
// Kernel 1 (fused): blocks 0..127 -> hid_gemm tile; blocks 128..139 -> SW sums
//   g_Hc[row][o] = hidden[row][:] @ W1[0:1024][o] + b1[o]
//   g_SW[s][o]   = sum_{r=0..63} W1[1024 + s*64 + r][o]
// ---------------------------------------------------------------------------
__global__ __launch_bounds__(256) void prep_kernel(const float* __restrict__ A,
                                                   const float* __restrict__ W1,
                                                   const float* __restrict__ b1) {
    __shared__ float As[2][32 * 36];
    __shared__ float Bs[2][32 * 128];
    __shared__ float red[128];

    const int tid = threadIdx.x;

    if (blockIdx.x >= 128) {
        // ---- SW part: one block per stat-row s, 2-way split over rows ----
        int s = blockIdx.x - 128;             // 0..11
        int o = tid & 127;
        int half = tid >> 7;                  // 0 or 1
        const float* p = W1 + (size_t)(1024 + s * 64 + half * 32) * OUTC + o;
        float acc = 0.f;
#pragma unroll 8
        for (int r = 0; r < 32; r++) acc += p[(size_t)r * OUTC];
        if (half) red[o] = acc;
        __syncthreads();
        if (!half) g_SW[s * OUTC + o] = acc + red[o];
        return;
    }

    // ---- hidden GEMM part ----
    const int m0  = blockIdx.x * 32;
    const int tr  = tid >> 4;
    const int tc  = tid & 15;

    const int lar = tid >> 3;
    const int lac = (tid & 7) << 2;
    const int lbr = tid >> 3;
    const int lbc = (tid & 7) << 2;

    const float* Ag = A  + (size_t)(m0 + lar) * HIDD + lac;
    const float* Bg = W1 + (size_t)lbr * OUTC + lbc;

    ull acc[2][4];
#pragma unroll
    for (int i = 0; i < 2; i++)
#pragma unroll
        for (int j = 0; j < 4; j++) acc[i][j] = 0ull;

    float4 aR  = *(const float4*)(Ag);
    float4 bR0 = *(const float4*)(Bg);
    float4 bR1 = *(const float4*)(Bg + 32);
    float4 bR2 = *(const float4*)(Bg + 64);
    float4 bR3 = *(const float4*)(Bg + 96);
    *(float4*)&As[0][lar * 36 + lac] = aR;
    *(float4*)&Bs[0][lbr * 128 + lbc]      = bR0;
    *(float4*)&Bs[0][lbr * 128 + lbc + 32] = bR1;
    *(float4*)&Bs[0][lbr * 128 + lbc + 64] = bR2;
    *(float4*)&Bs[0][lbr * 128 + lbc + 96] = bR3;
    __syncthreads();

    for (int c = 0; c < 32; c++) {
        if (c + 1 < 32) {
            const float* ag = Ag + (c + 1) * 32;
            const float* bg = Bg + (size_t)(c + 1) * 32 * OUTC;
            aR  = *(const float4*)(ag);
            bR0 = *(const float4*)(bg);
            bR1 = *(const float4*)(bg + 32);
            bR2 = *(const float4*)(bg + 64);
            bR3 = *(const float4*)(bg + 96);
        }
        const float* as = As[c & 1];
        const float* bs = Bs[c & 1];
#pragma unroll
        for (int kk = 0; kk < 32; kk++) {
            float a0 = as[(tr * 2) * 36 + kk];
            float a1 = as[(tr * 2 + 1) * 36 + kk];
            ull a0d = pack2(a0, a0);
            ull a1d = pack2(a1, a1);
            ulonglong2 bl = *(const ulonglong2*)&bs[kk * 128 + tc * 4];
            ulonglong2 bh = *(const ulonglong2*)&bs[kk * 128 + 64 + tc * 4];
            acc[0][0] = fma2(a0d, bl.x, acc[0][0]);
            acc[0][1] = fma2(a0d, bl.y, acc[0][1]);
            acc[0][2] = fma2(a0d, bh.x, acc[0][2]);
            acc[0][3] = fma2(a0d, bh.y, acc[0][3]);
            acc[1][0] = fma2(a1d, bl.x, acc[1][0]);
            acc[1][1] = fma2(a1d, bl.y, acc[1][1]);
            acc[1][2] = fma2(a1d, bh.x, acc[1][2]);
            acc[1][3] = fma2(a1d, bh.y, acc[1][3]);
        }
        __syncthreads();
        if (c + 1 < 32) {
            int nb = (c + 1) & 1;
            *(float4*)&As[nb][lar * 36 + lac] = aR;
            *(float4*)&Bs[nb][lbr * 128 + lbc]      = bR0;
            *(float4*)&Bs[nb][lbr * 128 + lbc + 32] = bR1;
            *(float4*)&Bs[nb][lbr * 128 + lbc + 64] = bR2;
            *(float4*)&Bs[nb][lbr * 128 + lbc + 96] = bR3;
            __syncthreads();
        }
    }

    float4 blo = *(const float4*)(b1 + tc * 4);
    float4 bhi = *(const float4*)(b1 + 64 + tc * 4);
#pragma unroll
    for (int i = 0; i < 2; i++) {
        int row = m0 + tr * 2 + i;
        float2 a = unp2(acc[i][0]), b = unp2(acc[i][1]);
        float2 c2 = unp2(acc[i][2]), d = unp2(acc[i][3]);
        float4 lo = make_float4(a.x + blo.x, a.y + blo.y, b.x + blo.z, b.y + blo.w);
        float4 hi = make_float4(c2.x + bhi.x, c2.y + bhi.y, d.x + bhi.z, d.y + bhi.w);
        *(float4*)&g_Hc[(size_t)row * OUTC + tc * 4]      = lo;
        *(float4*)&g_Hc[(size_t)row * OUTC + 64 + tc * 4] = hi;
    }
}

// ---------------------------------------------------------------------------
// Kernel 2: persistent gate kernel.
// Block: 256 threads (8 warps). Wext[268][128] in smem.
// Warp w: row-slot w>>1, head-half w&1 (8 heads). 64 fp32 accs as 32 f32x2.
// Chunk loop register-double-buffered (wv/xv prefetched one chunk ahead).
// ---------------------------------------------------------------------------
__global__ __launch_bounds__(256, 1) void gate_kernel(
    const float* __restrict__ br0, const float* __restrict__ br1,
    const float* __restrict__ br2, const float* __restrict__ br3,
    const float* __restrict__ W1,  const float* __restrict__ W2,
    const float* __restrict__ b2,  const float* __restrict__ eps,
    const float* __restrict__ temp, float* __restrict__ out)
{
    extern __shared__ float smf[];
    float* ws = smf;                       // [KEXT][128]
    float* xs = smf + KEXT * OUTC;         // [4 slots][16 heads][XPAD]

    const int tid = threadIdx.x;

    // cooperative load of Wext: rows 0..255 = W1[1792..2047], rows 256..267 = SW
    {
        const float4* src = (const float4*)(W1 + (size_t)1792 * OUTC);
        float4* dst = (float4*)ws;
        for (int i = tid; i < 256 * OUTC / 4; i += 256) dst[i] = src[i];
        const float4* s2 = (const float4*)g_SW;
        float4* d2 = (float4*)(ws + 256 * OUTC);
        for (int i = tid; i < 12 * OUTC / 4; i += 256) d2[i] = s2[i];
    }

    const int warp = tid >> 5, lane = tid & 31;
    const int slot = warp >> 1, hg = warp & 1;
    const int h_idx = lane >> 2, q = lane & 3;
    const int h_abs = hg * 8 + h_idx;

    float4 w2v[4];
#pragma unroll
    for (int j = 0; j < 4; j++) w2v[j] = ((const float4*)W2)[lane * 4 + j];
    const float4 b2v = *(const float4*)b2;

    // hoisted per-head softmax constants (lanes 0..7 only use them)
    float it_h = 1.f;
    float4 fl_h = make_float4(0.f, 0.f, 0.f, 0.f);
    if (lane < 8) {
        int head = hg * 8 + lane;
        float t = fminf(fmaxf(temp[head], 0.2f), 10.0f);
        it_h = 1.f / t;
        float4 ef = *(const float4*)(eps + head * 4);
        fl_h.x = fminf(fmaxf(ef.x, 1e-7f), 0.1f);
        fl_h.y = fminf(fmaxf(ef.y, 1e-7f), 0.1f);
        fl_h.z = fminf(fmaxf(ef.z, 1e-7f), 0.1f);
        fl_h.w = fminf(fmaxf(ef.w, 1e-7f), 0.1f);
    }
    __syncthreads();

    float* xw = xs + slot * (HHH * XPAD);
    const float* wsl = ws + lane * 4;

    for (int base = blockIdx.x * 4; base < NBL; base += gridDim.x * 4) {
        const int row = base + slot;
        __syncwarp();

        // ---- load raw branch data + compute stats from registers ----
        float stt[4][3];
#pragma unroll
        for (int p = 0; p < 4; p++) {
            const float* bp = (p == 0) ? br0 : (p == 1) ? br1 : (p == 2) ? br2 : br3;
            const float* g = bp + (size_t)row * 1024 + h_abs * 64 + q * 16;
            float sum = 0.f, sq = 0.f, mx = -INFINITY;
#pragma unroll
            for (int j = 0; j < 4; j++) {
                float4 v = *(const float4*)(g + j * 4);
                *(float4*)&xw[h_abs * XPAD + p * 64 + q * 16 + j * 4] = v;
                sum += (v.x + v.y) + (v.z + v.w);
                sq  += v.x * v.x + v.y * v.y + v.z * v.z + v.w * v.w;
                mx = fmaxf(mx, fmaxf(fmaxf(v.x, v.y), fmaxf(v.z, v.w)));
            }
            sum += __shfl_xor_sync(0xffffffffu, sum, 1);
            sum += __shfl_xor_sync(0xffffffffu, sum, 2);
            sq  += __shfl_xor_sync(0xffffffffu, sq, 1);
            sq  += __shfl_xor_sync(0xffffffffu, sq, 2);
            mx = fmaxf(mx, __shfl_xor_sync(0xffffffffu, mx, 1));
            mx = fmaxf(mx, __shfl_xor_sync(0xffffffffu, mx, 2));
            stt[p][0] = sum * (1.f / 64.f);
            stt[p][1] = sqrtf(fmaxf(sq * (1.f / 64.f), 1e-8f));
            stt[p][2] = mx;
        }
        if (q == 0) {
#pragma unroll
            for (int p = 0; p < 4; p++) {
                xw[h_abs * XPAD + 256 + p * 3 + 0] = stt[p][0];
                xw[h_abs * XPAD + 256 + p * 3 + 1] = stt[p][1];
                xw[h_abs * XPAD + 256 + p * 3 + 2] = stt[p][2];
            }
        }
        __syncwarp();

        // ---- init accumulators with hidden contribution (includes b1) ----
        ull acc[8][2];
        {
            ulonglong2 hc = *(const ulonglong2*)(g_Hc + (size_t)row * OUTC + lane * 4);
#pragma unroll
            for (int h = 0; h < 8; h++) { acc[h][0] = hc.x; acc[h][1] = hc.y; }
        }

        const float4* xb[8];
#pragma unroll
        for (int h = 0; h < 8; h++) xb[h] = (const float4*)&xw[(hg * 8 + h) * XPAD];

        // ---- main K loop, register double-buffered ----
        float4 xv[2][8];
        ulonglong2 wv[2][4];
#pragma unroll
        for (int h = 0; h < 8; h++) xv[0][h] = xb[h][0];
#pragma unroll
        for (int j = 0; j < 4; j++) wv[0][j] = *(const ulonglong2*)&wsl[j * OUTC];

        for (int kc = 0; kc < KCH - 1; kc++) {
            const int cur = kc & 1, nxt = cur ^ 1;
            // prefetch next chunk
#pragma unroll
            for (int h = 0; h < 8; h++) xv[nxt][h] = xb[h][kc + 1];
#pragma unroll
            for (int j = 0; j < 4; j++)
                wv[nxt][j] = *(const ulonglong2*)&wsl[((kc + 1) * 4 + j) * OUTC];
            // compute current chunk
#pragma unroll
            for (int j = 0; j < 4; j++) {
#pragma unroll
                for (int h = 0; h < 8; h++) {
                    float xvv = (j == 0) ? xv[cur][h].x : (j == 1) ? xv[cur][h].y
                              : (j == 2) ? xv[cur][h].z : xv[cur][h].w;
                    ull x2 = pack2(xvv, xvv);
                    acc[h][0] = fma2(x2, wv[cur][j].x, acc[h][0]);
                    acc[h][1] = fma2(x2, wv[cur][j].y, acc[h][1]);
                }
            }
        }
        {   // last chunk (kc = KCH-1, parity (KCH-1)&1 = 0)
            const int cur = (KCH - 1) & 1;
#pragma unroll
            for (int j = 0; j < 4; j++) {
#pragma unroll
                for (int h = 0; h < 8; h++) {
                    float xvv = (j == 0) ? xv[cur][h].x : (j == 1) ? xv[cur][h].y
                              : (j == 2) ? xv[cur][h].z : xv[cur][h].w;
                    ull x2 = pack2(xvv, xvv);
                    acc[h][0] = fma2(x2, wv[cur][j].x, acc[h][0]);
                    acc[h][1] = fma2(x2, wv[cur][j].y, acc[h][1]);
                }
            }
        }

        // ---- epilogue: gelu, x W2, warp-reduce, softmax/floor ----
        float L0 = 0.f, L1 = 0.f, L2 = 0.f, L3 = 0.f;
#pragma unroll
        for (int h = 0; h < 8; h++) {
            float2 a01 = unp2(acc[h][0]);
            float2 a23 = unp2(acc[h][1]);
            float g0 = gelu_f(a01.x), g1 = gelu_f(a01.y);
            float g2 = gelu_f(a23.x), g3 = gelu_f(a23.y);
            float p0 = g0 * w2v[0].x + g1 * w2v[1].x + g2 * w2v[2].x + g3 * w2v[3].x;
            float p1 = g0 * w2v[0].y + g1 * w2v[1].y + g2 * w2v[2].y + g3 * w2v[3].y;
            float p2 = g0 * w2v[0].z + g1 * w2v[1].z + g2 * w2v[2].z + g3 * w2v[3].z;
            float p3 = g0 * w2v[0].w + g1 * w2v[1].w + g2 * w2v[2].w + g3 * w2v[3].w;
#pragma unroll
            for (int off = 16; off >= 1; off >>= 1) {
                p0 += __shfl_xor_sync(0xffffffffu, p0, off);
                p1 += __shfl_xor_sync(0xffffffffu, p1, off);
                p2 += __shfl_xor_sync(0xffffffffu, p2, off);
                p3 += __shfl_xor_sync(0xffffffffu, p3, off);
            }
            if (lane == h) {
                L0 = p0 + b2v.x; L1 = p1 + b2v.y;
                L2 = p2 + b2v.z; L3 = p3 + b2v.w;
            }
        }
        if (lane < 8) {
            int head = hg * 8 + lane;
            float s0 = L0 * it_h, s1 = L1 * it_h, s2 = L2 * it_h, s3 = L3 * it_h;
            float m = fmaxf(fmaxf(s0, s1), fmaxf(s2, s3));
            float e0 = expf(s0 - m), e1 = expf(s1 - m);
            float e2 = expf(s2 - m), e3 = expf(s3 - m);
            float inv = 1.f / (e0 + e1 + e2 + e3);
            float w0 = fmaxf(e0 * inv, fl_h.x);
            float w1 = fmaxf(e1 * inv, fl_h.y);
            float w2_ = fmaxf(e2 * inv, fl_h.z);
            float w3 = fmaxf(e3 * inv, fl_h.w);
            float inv2 = 1.f / (w0 + w1 + w2_ + w3);
            float4 o = make_float4(w0 * inv2, w1 * inv2, w2_ * inv2, w3 * inv2);
            *(float4*)(out + (size_t)row * 64 + head * 4) = o;
        }
    }
}

// ---------------------------------------------------------------------------
extern "C" void kernel_launch(void* const* d_in, const int* in_sizes, int n_in,
                              void* d_out, int out_size) {
    (void)in_sizes; (void)n_in; (void)out_size;
    const float* hidden = (const float*)d_in[0];
    const float* b0     = (const float*)d_in[1];
    const float* b1br   = (const float*)d_in[2];
    const float* b2br   = (const float*)d_in[3];
    const float* b3br   = (const float*)d_in[4];
    const float* W1     = (const float*)d_in[5];
    const float* b1     = (const float*)d_in[6];
    const float* W2     = (const float*)d_in[7];
    const float* b2     = (const float*)d_in[8];
    const float* eps    = (const float*)d_in[9];
    const float* temp   = (const float*)d_in[10];
    float* out = (float*)d_out;

    const int gate_smem = (KEXT * OUTC + 4 * HHH * XPAD) * (int)sizeof(float); // 206848
    cudaFuncSetAttribute(gate_kernel, cudaFuncAttributeMaxDynamicSharedMemorySize,
                         gate_smem);

    prep_kernel<<<140, 256>>>(hidden, W1, b1);
    gate_kernel<<<148, 256, gate_smem>>>(b0, b1br, b2br, b3br, W1, W2, b2, eps,
                                         temp, out);
}

// round 4
// speedup vs baseline: 3.6277x; 3.6277x over previous
#include <cuda_runtime.h>
#include <math.h>

#define NBL   4096          // B*L
#define HHH   16            // heads
#define HIDD  1024
#define OUTC  128           // 2*D hidden layer width
#define KEXT  268           // 256 branch rows + 12 stat rows
#define KCH   67            // KEXT/4
#define XPAD  272           // padded per-head x row (multiple of 4)

typedef unsigned long long ull;

// scratch (device globals: allocation-free rule)
__device__ __align__(16) float g_Hc[NBL * OUTC];   // hidden @ W1[0:1024] + b1
__device__ __align__(16) float g_SW[12 * OUTC];    // stat-row column sums

// ---------- packed f32x2 helpers ----------
__device__ __forceinline__ ull pack2(float a, float b) {
    ull r;
    asm("mov.b64 %0, {%1, %2};" : "=l"(r)
        : "r"(__float_as_uint(a)), "r"(__float_as_uint(b)));
    return r;
}
__device__ __forceinline__ ull fma2(ull a, ull b, ull c) {
    ull d;
    asm("fma.rn.f32x2 %0, %1, %2, %3;" : "=l"(d) : "l"(a), "l"(b), "l"(c));
    return d;
}
__device__ __forceinline__ float2 unp2(ull a) {
    unsigned lo, hi;
    asm("mov.b64 {%0, %1}, %2;" : "=r"(lo), "=r"(hi) : "l"(a));
    return make_float2(__uint_as_float(lo), __uint_as_float(hi));
}
__device__ __forceinline__ float gelu_f(float x) {
    return 0.5f * x * (1.0f + erff(x * 0.70710678118654752440f));
}

// ---------------------------------------------------------------------------
// Kernel 1 (fused): blocks 0..127 -> hid_gemm tile; blocks 128..139 -> SW sums
// ---------------------------------------------------------------------------
__global__ __launch_bounds__(256) void prep_kernel(const float* __restrict__ A,
                                                   const float* __restrict__ W1,
                                                   const float* __restrict__ b1) {
    __shared__ float As[2][32 * 36];
    __shared__ float Bs[2][32 * 128];
    __shared__ float red[128];

    const int tid = threadIdx.x;

    if (blockIdx.x >= 128) {
        int s = blockIdx.x - 128;             // 0..11
        int o = tid & 127;
        int half = tid >> 7;
        const float* p = W1 + (size_t)(1024 + s * 64 + half * 32) * OUTC + o;
        float acc = 0.f;
#pragma unroll 8
        for (int r = 0; r < 32; r++) acc += p[(size_t)r * OUTC];
        if (half) red[o] = acc;
        __syncthreads();
        if (!half) g_SW[s * OUTC + o] = acc + red[o];
        return;
    }

    const int m0  = blockIdx.x * 32;
    const int tr  = tid >> 4;
    const int tc  = tid & 15;

    const int lar = tid >> 3;
    const int lac = (tid & 7) << 2;
    const int lbr = tid >> 3;
    const int lbc = (tid & 7) << 2;

    const float* Ag = A  + (size_t)(m0 + lar) * HIDD + lac;
    const float* Bg = W1 + (size_t)lbr * OUTC + lbc;

    ull acc[2][4];
#pragma unroll
    for (int i = 0; i < 2; i++)
#pragma unroll
        for (int j = 0; j < 4; j++) acc[i][j] = 0ull;

    float4 aR  = *(const float4*)(Ag);
    float4 bR0 = *(const float4*)(Bg);
    float4 bR1 = *(const float4*)(Bg + 32);
    float4 bR2 = *(const float4*)(Bg + 64);
    float4 bR3 = *(const float4*)(Bg + 96);
    *(float4*)&As[0][lar * 36 + lac] = aR;
    *(float4*)&Bs[0][lbr * 128 + lbc]      = bR0;
    *(float4*)&Bs[0][lbr * 128 + lbc + 32] = bR1;
    *(float4*)&Bs[0][lbr * 128 + lbc + 64] = bR2;
    *(float4*)&Bs[0][lbr * 128 + lbc + 96] = bR3;
    __syncthreads();

    for (int c = 0; c < 32; c++) {
        if (c + 1 < 32) {
            const float* ag = Ag + (c + 1) * 32;
            const float* bg = Bg + (size_t)(c + 1) * 32 * OUTC;
            aR  = *(const float4*)(ag);
            bR0 = *(const float4*)(bg);
            bR1 = *(const float4*)(bg + 32);
            bR2 = *(const float4*)(bg + 64);
            bR3 = *(const float4*)(bg + 96);
        }
        const float* as = As[c & 1];
        const float* bs = Bs[c & 1];
#pragma unroll
        for (int kk = 0; kk < 32; kk++) {
            float a0 = as[(tr * 2) * 36 + kk];
            float a1 = as[(tr * 2 + 1) * 36 + kk];
            ull a0d = pack2(a0, a0);
            ull a1d = pack2(a1, a1);
            ulonglong2 bl = *(const ulonglong2*)&bs[kk * 128 + tc * 4];
            ulonglong2 bh = *(const ulonglong2*)&bs[kk * 128 + 64 + tc * 4];
            acc[0][0] = fma2(a0d, bl.x, acc[0][0]);
            acc[0][1] = fma2(a0d, bl.y, acc[0][1]);
            acc[0][2] = fma2(a0d, bh.x, acc[0][2]);
            acc[0][3] = fma2(a0d, bh.y, acc[0][3]);
            acc[1][0] = fma2(a1d, bl.x, acc[1][0]);
            acc[1][1] = fma2(a1d, bl.y, acc[1][1]);
            acc[1][2] = fma2(a1d, bh.x, acc[1][2]);
            acc[1][3] = fma2(a1d, bh.y, acc[1][3]);
        }
        __syncthreads();
        if (c + 1 < 32) {
            int nb = (c + 1) & 1;
            *(float4*)&As[nb][lar * 36 + lac] = aR;
            *(float4*)&Bs[nb][lbr * 128 + lbc]      = bR0;
            *(float4*)&Bs[nb][lbr * 128 + lbc + 32] = bR1;
            *(float4*)&Bs[nb][lbr * 128 + lbc + 64] = bR2;
            *(float4*)&Bs[nb][lbr * 128 + lbc + 96] = bR3;
            __syncthreads();
        }
    }

    float4 blo = *(const float4*)(b1 + tc * 4);
    float4 bhi = *(const float4*)(b1 + 64 + tc * 4);
#pragma unroll
    for (int i = 0; i < 2; i++) {
        int row = m0 + tr * 2 + i;
        float2 a = unp2(acc[i][0]), b = unp2(acc[i][1]);
        float2 c2 = unp2(acc[i][2]), d = unp2(acc[i][3]);
        float4 lo = make_float4(a.x + blo.x, a.y + blo.y, b.x + blo.z, b.y + blo.w);
        float4 hi = make_float4(c2.x + bhi.x, c2.y + bhi.y, d.x + bhi.z, d.y + bhi.w);
        *(float4*)&g_Hc[(size_t)row * OUTC + tc * 4]      = lo;
        *(float4*)&g_Hc[(size_t)row * OUTC + 64 + tc * 4] = hi;
    }
}

// ---------------------------------------------------------------------------
// Kernel 2: persistent gate kernel. 256 threads (8 warps), Wext in smem.
// Main K loop software-pipelined with TWO STATICALLY-NAMED register stages
// (all indices compile-time -> no local memory).
// ---------------------------------------------------------------------------

#define LOADX(XV, KC) do {                                            \
    _Pragma("unroll")                                                  \
    for (int h_ = 0; h_ < 8; h_++) XV[h_] = xb[h_][(KC)];              \
} while (0)

#define LOADW(WV, KC) do {                                            \
    _Pragma("unroll")                                                  \
    for (int j_ = 0; j_ < 4; j_++)                                     \
        WV[j_] = *(const ulonglong2*)&wsl[((KC) * 4 + j_) * OUTC];     \
} while (0)

#define COMP(XV, WV) do {                                             \
    _Pragma("unroll")                                                  \
    for (int j_ = 0; j_ < 4; j_++) {                                   \
        _Pragma("unroll")                                              \
        for (int h_ = 0; h_ < 8; h_++) {                               \
            float xvv_ = (j_ == 0) ? XV[h_].x : (j_ == 1) ? XV[h_].y   \
                       : (j_ == 2) ? XV[h_].z : XV[h_].w;              \
            ull x2_ = pack2(xvv_, xvv_);                               \
            acc[h_][0] = fma2(x2_, WV[j_].x, acc[h_][0]);              \
            acc[h_][1] = fma2(x2_, WV[j_].y, acc[h_][1]);              \
        }                                                              \
    }                                                                  \
} while (0)

__global__ __launch_bounds__(256, 1) void gate_kernel(
    const float* __restrict__ br0, const float* __restrict__ br1,
    const float* __restrict__ br2, const float* __restrict__ br3,
    const float* __restrict__ W1,  const float* __restrict__ W2,
    const float* __restrict__ b2,  const float* __restrict__ eps,
    const float* __restrict__ temp, float* __restrict__ out)
{
    extern __shared__ float smf[];
    float* ws = smf;                       // [KEXT][128]
    float* xs = smf + KEXT * OUTC;         // [4 slots][16 heads][XPAD]

    const int tid = threadIdx.x;

    // cooperative load of Wext: rows 0..255 = W1[1792..2047], rows 256..267 = SW
    {
        const float4* src = (const float4*)(W1 + (size_t)1792 * OUTC);
        float4* dst = (float4*)ws;
        for (int i = tid; i < 256 * OUTC / 4; i += 256) dst[i] = src[i];
        const float4* s2 = (const float4*)g_SW;
        float4* d2 = (float4*)(ws + 256 * OUTC);
        for (int i = tid; i < 12 * OUTC / 4; i += 256) d2[i] = s2[i];
    }

    const int warp = tid >> 5, lane = tid & 31;
    const int slot = warp >> 1, hg = warp & 1;
    const int h_idx = lane >> 2, q = lane & 3;
    const int h_abs = hg * 8 + h_idx;

    float4 w2v[4];
#pragma unroll
    for (int j = 0; j < 4; j++) w2v[j] = ((const float4*)W2)[lane * 4 + j];
    const float4 b2v = *(const float4*)b2;

    // hoisted per-head softmax constants (lanes 0..7 only use them)
    float it_h = 1.f;
    float4 fl_h = make_float4(0.f, 0.f, 0.f, 0.f);
    if (lane < 8) {
        int head = hg * 8 + lane;
        float t = fminf(fmaxf(temp[head], 0.2f), 10.0f);
        it_h = 1.f / t;
        float4 ef = *(const float4*)(eps + head * 4);
        fl_h.x = fminf(fmaxf(ef.x, 1e-7f), 0.1f);
        fl_h.y = fminf(fmaxf(ef.y, 1e-7f), 0.1f);
        fl_h.z = fminf(fmaxf(ef.z, 1e-7f), 0.1f);
        fl_h.w = fminf(fmaxf(ef.w, 1e-7f), 0.1f);
    }
    __syncthreads();

    float* xw = xs + slot * (HHH * XPAD);
    const float* wsl = ws + lane * 4;

    for (int base = blockIdx.x * 4; base < NBL; base += gridDim.x * 4) {
        const int row = base + slot;
        __syncwarp();

        // prefetch hidden contribution early (hides L2 latency under stats)
        const ulonglong2 hc = *(const ulonglong2*)(g_Hc + (size_t)row * OUTC + lane * 4);

        // ---- load raw branch data + compute stats from registers ----
        float stt[4][3];
#pragma unroll
        for (int p = 0; p < 4; p++) {
            const float* bp = (p == 0) ? br0 : (p == 1) ? br1 : (p == 2) ? br2 : br3;
            const float* g = bp + (size_t)row * 1024 + h_abs * 64 + q * 16;
            float sum = 0.f, sq = 0.f, mx = -INFINITY;
#pragma unroll
            for (int j = 0; j < 4; j++) {
                float4 v = *(const float4*)(g + j * 4);
                *(float4*)&xw[h_abs * XPAD + p * 64 + q * 16 + j * 4] = v;
                sum += (v.x + v.y) + (v.z + v.w);
                sq  += v.x * v.x + v.y * v.y + v.z * v.z + v.w * v.w;
                mx = fmaxf(mx, fmaxf(fmaxf(v.x, v.y), fmaxf(v.z, v.w)));
            }
            sum += __shfl_xor_sync(0xffffffffu, sum, 1);
            sum += __shfl_xor_sync(0xffffffffu, sum, 2);
            sq  += __shfl_xor_sync(0xffffffffu, sq, 1);
            sq  += __shfl_xor_sync(0xffffffffu, sq, 2);
            mx = fmaxf(mx, __shfl_xor_sync(0xffffffffu, mx, 1));
            mx = fmaxf(mx, __shfl_xor_sync(0xffffffffu, mx, 2));
            stt[p][0] = sum * (1.f / 64.f);
            stt[p][1] = sqrtf(fmaxf(sq * (1.f / 64.f), 1e-8f));
            stt[p][2] = mx;
        }
        if (q == 0) {
#pragma unroll
            for (int p = 0; p < 4; p++) {
                xw[h_abs * XPAD + 256 + p * 3 + 0] = stt[p][0];
                xw[h_abs * XPAD + 256 + p * 3 + 1] = stt[p][1];
                xw[h_abs * XPAD + 256 + p * 3 + 2] = stt[p][2];
            }
        }
        __syncwarp();

        // ---- init accumulators with hidden contribution (includes b1) ----
        ull acc[8][2];
#pragma unroll
        for (int h = 0; h < 8; h++) { acc[h][0] = hc.x; acc[h][1] = hc.y; }

        const float4* xb[8];
#pragma unroll
        for (int h = 0; h < 8; h++) xb[h] = (const float4*)&xw[(hg * 8 + h) * XPAD];

        // ---- main K loop: software-pipelined, static register stages ----
        float4 xvA[8], xvB[8];
        ulonglong2 wvA[4], wvB[4];
        LOADX(xvA, 0); LOADW(wvA, 0);
#pragma unroll 1
        for (int kc = 0; kc + 2 < KCH; kc += 2) {     // kc = 0,2,...,64
            LOADX(xvB, kc + 1); LOADW(wvB, kc + 1);
            COMP(xvA, wvA);                            // chunk kc
            LOADX(xvA, kc + 2); LOADW(wvA, kc + 2);
            COMP(xvB, wvB);                            // chunk kc+1
        }
        COMP(xvA, wvA);                                // chunk 66

        // ---- epilogue: gelu, x W2, warp-reduce, softmax/floor ----
        float L0 = 0.f, L1 = 0.f, L2 = 0.f, L3 = 0.f;
#pragma unroll
        for (int h = 0; h < 8; h++) {
            float2 a01 = unp2(acc[h][0]);
            float2 a23 = unp2(acc[h][1]);
            float g0 = gelu_f(a01.x), g1 = gelu_f(a01.y);
            float g2 = gelu_f(a23.x), g3 = gelu_f(a23.y);
            float p0 = g0 * w2v[0].x + g1 * w2v[1].x + g2 * w2v[2].x + g3 * w2v[3].x;
            float p1 = g0 * w2v[0].y + g1 * w2v[1].y + g2 * w2v[2].y + g3 * w2v[3].y;
            float p2 = g0 * w2v[0].z + g1 * w2v[1].z + g2 * w2v[2].z + g3 * w2v[3].z;
            float p3 = g0 * w2v[0].w + g1 * w2v[1].w + g2 * w2v[2].w + g3 * w2v[3].w;
#pragma unroll
            for (int off = 16; off >= 1; off >>= 1) {
                p0 += __shfl_xor_sync(0xffffffffu, p0, off);
                p1 += __shfl_xor_sync(0xffffffffu, p1, off);
                p2 += __shfl_xor_sync(0xffffffffu, p2, off);
                p3 += __shfl_xor_sync(0xffffffffu, p3, off);
            }
            if (lane == h) {
                L0 = p0 + b2v.x; L1 = p1 + b2v.y;
                L2 = p2 + b2v.z; L3 = p3 + b2v.w;
            }
        }
        if (lane < 8) {
            int head = hg * 8 + lane;
            float s0 = L0 * it_h, s1 = L1 * it_h, s2 = L2 * it_h, s3 = L3 * it_h;
            float m = fmaxf(fmaxf(s0, s1), fmaxf(s2, s3));
            float e0 = expf(s0 - m), e1 = expf(s1 - m);
            float e2 = expf(s2 - m), e3 = expf(s3 - m);
            float inv = 1.f / (e0 + e1 + e2 + e3);
            float w0 = fmaxf(e0 * inv, fl_h.x);
            float w1 = fmaxf(e1 * inv, fl_h.y);
            float w2_ = fmaxf(e2 * inv, fl_h.z);
            float w3 = fmaxf(e3 * inv, fl_h.w);
            float inv2 = 1.f / (w0 + w1 + w2_ + w3);
            float4 o = make_float4(w0 * inv2, w1 * inv2, w2_ * inv2, w3 * inv2);
            *(float4*)(out + (size_t)row * 64 + head * 4) = o;
        }
    }
}

// ---------------------------------------------------------------------------
extern "C" void kernel_launch(void* const* d_in, const int* in_sizes, int n_in,
                              void* d_out, int out_size) {
    (void)in_sizes; (void)n_in; (void)out_size;
    const float* hidden = (const float*)d_in[0];
    const float* b0     = (const float*)d_in[1];
    const float* b1br   = (const float*)d_in[2];
    const float* b2br   = (const float*)d_in[3];
    const float* b3br   = (const float*)d_in[4];
    const float* W1     = (const float*)d_in[5];
    const float* b1     = (const float*)d_in[6];
    const float* W2     = (const float*)d_in[7];
    const float* b2     = (const float*)d_in[8];
    const float* eps    = (const float*)d_in[9];
    const float* temp   = (const float*)d_in[10];
    float* out = (float*)d_out;

    const int gate_smem = (KEXT * OUTC + 4 * HHH * XPAD) * (int)sizeof(float); // 206848
    cudaFuncSetAttribute(gate_kernel, cudaFuncAttributeMaxDynamicSharedMemorySize,
                         gate_smem);

    prep_kernel<<<140, 256>>>(hidden, W1, b1);
    gate_kernel<<<148, 256, gate_smem>>>(b0, b1br, b2br, b3br, W1, W2, b2, eps,
                                         temp, out);
}

// round 6
// speedup vs baseline: 3.9391x; 1.0858x over previous
#include <cuda_runtime.h>
#include <math.h>
#include <stdint.h>

#define NBL  4096
#define HIDD 1024
#define OUTC 128
typedef unsigned long long ull;
typedef uint32_t u32;

// ---------------- device scratch (allocation-free rule) ----------------
__device__ __align__(16) float g_Hc[NBL * OUTC];   // hidden @ W1[0:1024] + b1
__device__ __align__(16) float g_Wt[34 * 16 * 64]; // W in B-fragment layout (tf32)

// ---------------- fp32 helpers (prep) ----------------
__device__ __forceinline__ ull pack2(float a, float b) {
    ull r;
    asm("mov.b64 %0, {%1, %2};" : "=l"(r)
        : "r"(__float_as_uint(a)), "r"(__float_as_uint(b)));
    return r;
}
__device__ __forceinline__ ull fma2(ull a, ull b, ull c) {
    ull d;
    asm("fma.rn.f32x2 %0, %1, %2, %3;" : "=l"(d) : "l"(a), "l"(b), "l"(c));
    return d;
}
__device__ __forceinline__ float2 unp2(ull a) {
    unsigned lo, hi;
    asm("mov.b64 {%0, %1}, %2;" : "=r"(lo), "=r"(hi) : "l"(a));
    return make_float2(__uint_as_float(lo), __uint_as_float(hi));
}
__device__ __forceinline__ float gelu_f(float x) {
    return 0.5f * x * (1.0f + erff(x * 0.70710678118654752440f));
}
__device__ __forceinline__ u32 to_tf32(float x) {
    u32 o;
    asm("cvt.rna.tf32.f32 %0, %1;" : "=r"(o) : "f"(x));
    return o;
}
__device__ __forceinline__ void mma8(float& d0, float& d1, float& d2, float& d3,
                                     u32 a0, u32 a1, u32 a2, u32 a3,
                                     u32 b0, u32 b1) {
    asm volatile("mma.sync.aligned.m16n8k8.row.col.f32.tf32.tf32.f32 "
                 "{%0,%1,%2,%3}, {%4,%5,%6,%7}, {%8,%9}, {%0,%1,%2,%3};"
                 : "+f"(d0), "+f"(d1), "+f"(d2), "+f"(d3)
                 : "r"(a0), "r"(a1), "r"(a2), "r"(a3), "r"(b0), "r"(b1));
}

// ---------------------------------------------------------------------------
// prep_kernel: g_Hc[row][o] = hidden[row][:] @ W1[0:1024][o] + b1[o]  (exact fp32)
// ---------------------------------------------------------------------------
__global__ __launch_bounds__(256) void prep_kernel(const float* __restrict__ A,
                                                   const float* __restrict__ W1,
                                                   const float* __restrict__ b1) {
    __shared__ float As[2][32 * 36];
    __shared__ float Bs[2][32 * 128];

    const int tid = threadIdx.x;
    const int m0  = blockIdx.x * 32;
    const int tr  = tid >> 4;
    const int tc  = tid & 15;
    const int lar = tid >> 3;
    const int lac = (tid & 7) << 2;
    const int lbr = tid >> 3;
    const int lbc = (tid & 7) << 2;

    const float* Ag = A  + (size_t)(m0 + lar) * HIDD + lac;
    const float* Bg = W1 + (size_t)lbr * OUTC + lbc;

    ull acc[2][4];
#pragma unroll
    for (int i = 0; i < 2; i++)
#pragma unroll
        for (int j = 0; j < 4; j++) acc[i][j] = 0ull;

    float4 aR  = *(const float4*)(Ag);
    float4 bR0 = *(const float4*)(Bg);
    float4 bR1 = *(const float4*)(Bg + 32);
    float4 bR2 = *(const float4*)(Bg + 64);
    float4 bR3 = *(const float4*)(Bg + 96);
    *(float4*)&As[0][lar * 36 + lac] = aR;
    *(float4*)&Bs[0][lbr * 128 + lbc]      = bR0;
    *(float4*)&Bs[0][lbr * 128 + lbc + 32] = bR1;
    *(float4*)&Bs[0][lbr * 128 + lbc + 64] = bR2;
    *(float4*)&Bs[0][lbr * 128 + lbc + 96] = bR3;
    __syncthreads();

    for (int c = 0; c < 32; c++) {
        if (c + 1 < 32) {
            const float* ag = Ag + (c + 1) * 32;
            const float* bg = Bg + (size_t)(c + 1) * 32 * OUTC;
            aR  = *(const float4*)(ag);
            bR0 = *(const float4*)(bg);
            bR1 = *(const float4*)(bg + 32);
            bR2 = *(const float4*)(bg + 64);
            bR3 = *(const float4*)(bg + 96);
        }
        const float* as = As[c & 1];
        const float* bs = Bs[c & 1];
#pragma unroll
        for (int kk = 0; kk < 32; kk++) {
            float a0 = as[(tr * 2) * 36 + kk];
            float a1 = as[(tr * 2 + 1) * 36 + kk];
            ull a0d = pack2(a0, a0);
            ull a1d = pack2(a1, a1);
            ulonglong2 bl = *(const ulonglong2*)&bs[kk * 128 + tc * 4];
            ulonglong2 bh = *(const ulonglong2*)&bs[kk * 128 + 64 + tc * 4];
            acc[0][0] = fma2(a0d, bl.x, acc[0][0]);
            acc[0][1] = fma2(a0d, bl.y, acc[0][1]);
            acc[0][2] = fma2(a0d, bh.x, acc[0][2]);
            acc[0][3] = fma2(a0d, bh.y, acc[0][3]);
            acc[1][0] = fma2(a1d, bl.x, acc[1][0]);
            acc[1][1] = fma2(a1d, bl.y, acc[1][1]);
            acc[1][2] = fma2(a1d, bh.x, acc[1][2]);
            acc[1][3] = fma2(a1d, bh.y, acc[1][3]);
        }
        __syncthreads();
        if (c + 1 < 32) {
            int nb = (c + 1) & 1;
            *(float4*)&As[nb][lar * 36 + lac] = aR;
            *(float4*)&Bs[nb][lbr * 128 + lbc]      = bR0;
            *(float4*)&Bs[nb][lbr * 128 + lbc + 32] = bR1;
            *(float4*)&Bs[nb][lbr * 128 + lbc + 64] = bR2;
            *(float4*)&Bs[nb][lbr * 128 + lbc + 96] = bR3;
            __syncthreads();
        }
    }

    float4 blo = *(const float4*)(b1 + tc * 4);
    float4 bhi = *(const float4*)(b1 + 64 + tc * 4);
#pragma unroll
    for (int i = 0; i < 2; i++) {
        int row = m0 + tr * 2 + i;
        float2 a = unp2(acc[i][0]), b = unp2(acc[i][1]);
        float2 c2 = unp2(acc[i][2]), d = unp2(acc[i][3]);
        float4 lo = make_float4(a.x + blo.x, a.y + blo.y, b.x + blo.z, b.y + blo.w);
        float4 hi = make_float4(c2.x + bhi.x, c2.y + bhi.y, d.x + bhi.z, d.y + bhi.w);
        *(float4*)&g_Hc[(size_t)row * OUTC + tc * 4]      = lo;
        *(float4*)&g_Hc[(size_t)row * OUTC + 64 + tc * 4] = hi;
    }
}

// ---------------------------------------------------------------------------
// wt_kernel: build W in mma B-fragment layout (tf32 bit patterns).
//  Wf[((kb*16+nb)*32 + l)*2 + w] = Wsrc(kb*8 + (l&3) + w*4, nb*8 + (l>>2))
//  Wsrc(k,n): k<256 -> W1[1792+k][n]; 256<=k<268 -> sum_r W1[1024+(k-256)*64+r][n];
//             else 0.
//  blocks 0..31: kb = blockIdx (branch rows). block 32: kb 32..33 (stats).
// ---------------------------------------------------------------------------
__global__ __launch_bounds__(256) void wt_kernel(const float* __restrict__ W1) {
    const int tid = threadIdx.x;
    u32* dst = (u32*)g_Wt;
    if (blockIdx.x < 32) {
        int kb = blockIdx.x;
#pragma unroll
        for (int i = 0; i < 4; i++) {
            int gi = tid + i * 256;           // 0..1023
            int nb = gi >> 6, rem = gi & 63, l = rem >> 1, w = rem & 1;
            int kabs = kb * 8 + (l & 3) + w * 4;
            int n = nb * 8 + (l >> 2);
            float v = W1[(size_t)(1792 + kabs) * 128 + n];
            dst[(kb * 16 + nb) * 64 + l * 2 + w] = to_tf32(v);
        }
    } else {
#pragma unroll 1
        for (int i = 0; i < 8; i++) {
            int gi = tid + i * 256;           // 0..2047
            int kbs = gi >> 10, rem = gi & 1023;
            int nb = rem >> 6, rem2 = rem & 63, l = rem2 >> 1, w = rem2 & 1;
            int sk = kbs * 8 + (l & 3) + w * 4;
            int n = nb * 8 + (l >> 2);
            float v = 0.f;
            if (sk < 12) {
                const float* p = W1 + (size_t)(1024 + sk * 64) * 128 + n;
#pragma unroll 8
                for (int r = 0; r < 64; r++) v += p[(size_t)r * 128];
            }
            dst[((32 + kbs) * 16 + nb) * 64 + l * 2 + w] = to_tf32(v);
        }
    }
}

// ---------------------------------------------------------------------------
// gate_mma: persistent tf32 mma.sync gate kernel. 148 CTAs x 256 threads.
// Tile: M=128 (8 bl x 16 heads), N=128, K=272 (4x64 branch + 12 stats + pad).
// Warp (mg=warp>>1, ng=warp&1): M rows [mg*32, mg*32+32), N cols [ng*64, +64).
// ---------------------------------------------------------------------------
#define OFF_W  0u        // 139264 B : W fragments
#define OFF_X  139264u   // 2 x 32768 B : X branch fragments (double buffer)
#define OFF_XS 204800u   // 8192 B : X stats fragments
#define OFF_HS 212992u   // 4096 B : g_Hc staging (8 x 128 f32)
#define OFF_LS 217088u   // 4096 B : logit exchange [2][128][4]
#define OFF_W2 221184u   // 2048 B : W2 [128][4]
#define SM_TOT 223232u

__global__ __launch_bounds__(256, 1) void gate_mma(
    const float* __restrict__ br0, const float* __restrict__ br1,
    const float* __restrict__ br2, const float* __restrict__ br3,
    const float* __restrict__ W2,  const float* __restrict__ b2,
    const float* __restrict__ eps, const float* __restrict__ temp,
    float* __restrict__ out)
{
    extern __shared__ char sm[];
    const int tid  = threadIdx.x;
    const int lane = tid & 31, warp = tid >> 5;
    const int mg = warp >> 1, ng = warp & 1;

    // ---- one-time init ----
    {   // W fragments -> smem (139264 B = 8704 float4)
        const float4* s = (const float4*)g_Wt;
        float4* d = (float4*)(sm + OFF_W);
        for (int i = tid; i < 8704; i += 256) d[i] = s[i];
    }
    {   // zero stats fragment region (pads stay 0)
        float4* d = (float4*)(sm + OFF_XS);
        for (int i = tid; i < 512; i += 256) d[i] = make_float4(0.f, 0.f, 0.f, 0.f);
    }
    {   // W2 [128][4]
        float* d = (float*)(sm + OFF_W2);
        for (int i = tid; i < 512; i += 256) d[i] = W2[i];
    }
    const float4 b2v = *(const float4*)b2;
    float it_h = 1.f;
    float4 fl_h = make_float4(0.f, 0.f, 0.f, 0.f);
    if (tid < 128) {
        int head = tid & 15;
        it_h = 1.f / fminf(fmaxf(temp[head], 0.2f), 10.0f);
        float4 ef = *(const float4*)(eps + head * 4);
        fl_h.x = fminf(fmaxf(ef.x, 1e-7f), 0.1f);
        fl_h.y = fminf(fmaxf(ef.y, 1e-7f), 0.1f);
        fl_h.z = fminf(fmaxf(ef.z, 1e-7f), 0.1f);
        fl_h.w = fminf(fmaxf(ef.w, 1e-7f), 0.1f);
    }
    __syncthreads();

    // ---- loader-thread constants: thread t handles row m = t>>1, half = t&1 ----
    const int lm = tid >> 1, half = tid & 1;
    const int lmt = lm >> 4;          // bl within tile (= A mtile index)
    const int lr  = lm & 15;          // head (= row within mtile)
    const int rlow = lr & 7, rhi = (lr >= 8) ? 1 : 0;
    const int swzr = rlow << 2;       // writer swizzle (words)
    const int swz_l = (lane * 4) ^ ((lane >> 2) << 2);  // reader swizzle (words)
    const int tig = lane & 3, gid = lane >> 2;

    float4 v[8];
    int tt = blockIdx.x;
    {   // prologue: LDG branch0 of first tile
        const float* src = br0 + (size_t)(tt * 8 + lmt) * 1024 + lr * 64 + half * 32;
#pragma unroll
        for (int j = 0; j < 8; j++) v[j] = *(const float4*)(src + j * 4);
    }

    for (; tt < 512; tt += 148) {
        const int base = tt * 8;

        // stage g_Hc slice [8][128] into smem
        {
            const float4* s = (const float4*)(g_Hc + (size_t)base * 128);
            ((float4*)(sm + OFF_HS))[tid] = s[tid];
        }

        float d0[8][4], d1[8][4];
#pragma unroll
        for (int nb = 0; nb < 8; nb++)
#pragma unroll
            for (int c = 0; c < 4; c++) { d0[nb][c] = 0.f; d1[nb][c] = 0.f; }

#pragma unroll 1
        for (int p = 0; p < 4; p++) {
            // ---- stats from registers (pair threads t, t^1 share a row) ----
            float s = 0.f, q2 = 0.f, mx = -INFINITY;
#pragma unroll
            for (int j = 0; j < 8; j++) {
                s  += (v[j].x + v[j].y) + (v[j].z + v[j].w);
                q2 += v[j].x * v[j].x + v[j].y * v[j].y
                    + v[j].z * v[j].z + v[j].w * v[j].w;
                mx = fmaxf(mx, fmaxf(fmaxf(v[j].x, v[j].y), fmaxf(v[j].z, v[j].w)));
            }
            s  += __shfl_xor_sync(0xffffffffu, s, 1);
            q2 += __shfl_xor_sync(0xffffffffu, q2, 1);
            mx  = fmaxf(mx, __shfl_xor_sync(0xffffffffu, mx, 1));

            // ---- write X fragments (tf32, bank-swizzled) ----
            {
                u32* xb = (u32*)(sm + OFF_X) + (p & 1) * 8192 + lmt * 1024;
                const float* vf = (const float*)v;
#pragma unroll
                for (int j = 0; j < 32; j++) {
                    int kbl = half * 4 + (j >> 3);
                    int off = (rlow * 16 + (j & 3) * 4 + rhi + (((j & 7) >= 4) ? 2 : 0)) ^ swzr;
                    xb[kbl * 128 + off] = to_tf32(vf[j]);
                }
                if (!half) {
                    float st0 = s * (1.f / 64.f);
                    float st1 = sqrtf(fmaxf(q2 * (1.f / 64.f), 1e-8f));
                    float st2 = mx;
                    u32* xs = (u32*)(sm + OFF_XS) + lmt * 256;
#pragma unroll
                    for (int t2 = 0; t2 < 3; t2++) {
                        int sk = p * 3 + t2;
                        int kbs = sk >> 3, kp = sk & 7;
                        int off = (rlow * 16 + (kp & 3) * 4 + rhi + ((kp >= 4) ? 2 : 0)) ^ swzr;
                        float sv = (t2 == 0) ? st0 : (t2 == 1) ? st1 : st2;
                        xs[kbs * 128 + off] = to_tf32(sv);
                    }
                }
            }
            __syncthreads();

            // ---- prefetch next branch (latency hidden under mma) ----
            if (p < 3) {
                const float* bp = (p == 0) ? br1 : (p == 1) ? br2 : br3;
                const float* src = bp + (size_t)(base + lmt) * 1024 + lr * 64 + half * 32;
#pragma unroll
                for (int j = 0; j < 8; j++) v[j] = *(const float4*)(src + j * 4);
            }

            // ---- mma section p ----
            {
                const char* xbase  = sm + OFF_X + (p & 1) * 32768u;
                const char* abase0 = xbase + (mg * 2) * 4096 + swz_l * 4;
                const char* abase1 = xbase + (mg * 2 + 1) * 4096 + swz_l * 4;
                const char* wbase  = sm + OFF_W + (u32)((p * 8 * 16 + ng * 8) * 256) + lane * 8;
#pragma unroll 2
                for (int kbl = 0; kbl < 8; kbl++) {
                    uint4 A0 = *(const uint4*)(abase0 + kbl * 512);
                    uint4 A1 = *(const uint4*)(abase1 + kbl * 512);
                    const char* wk = wbase + kbl * 4096;
#pragma unroll
                    for (int nb = 0; nb < 8; nb++) {
                        uint2 B = *(const uint2*)(wk + nb * 256);
                        mma8(d0[nb][0], d0[nb][1], d0[nb][2], d0[nb][3],
                             A0.x, A0.y, A0.z, A0.w, B.x, B.y);
                        mma8(d1[nb][0], d1[nb][1], d1[nb][2], d1[nb][3],
                             A1.x, A1.y, A1.z, A1.w, B.x, B.y);
                    }
                }
                if (p == 3) {   // stats section (kb 32..33, A from Xsf)
                    const char* sbase0 = sm + OFF_XS + (mg * 2) * 1024 + swz_l * 4;
                    const char* sbase1 = sm + OFF_XS + (mg * 2 + 1) * 1024 + swz_l * 4;
#pragma unroll
                    for (int kbs = 0; kbs < 2; kbs++) {
                        uint4 A0 = *(const uint4*)(sbase0 + kbs * 512);
                        uint4 A1 = *(const uint4*)(sbase1 + kbs * 512);
                        const char* wk = sm + OFF_W
                                       + (u32)(((32 + kbs) * 16 + ng * 8) * 256) + lane * 8;
#pragma unroll
                        for (int nb = 0; nb < 8; nb++) {
                            uint2 B = *(const uint2*)(wk + nb * 256);
                            mma8(d0[nb][0], d0[nb][1], d0[nb][2], d0[nb][3],
                                 A0.x, A0.y, A0.z, A0.w, B.x, B.y);
                            mma8(d1[nb][0], d1[nb][1], d1[nb][2], d1[nb][3],
                                 A1.x, A1.y, A1.z, A1.w, B.x, B.y);
                        }
                    }
                }
            }
        } // p loop

        // prefetch next tile's branch0 (hidden under epilogue)
        if (tt + 148 < 512) {
            const float* src = br0 + (size_t)((tt + 148) * 8 + lmt) * 1024
                             + lr * 64 + half * 32;
#pragma unroll
            for (int j = 0; j < 8; j++) v[j] = *(const float4*)(src + j * 4);
        }

        // ---- epilogue ----
        float LA0[4] = {0.f, 0.f, 0.f, 0.f}, LB0[4] = {0.f, 0.f, 0.f, 0.f};
        float LA1[4] = {0.f, 0.f, 0.f, 0.f}, LB1[4] = {0.f, 0.f, 0.f, 0.f};
        const float* Hsf = (const float*)(sm + OFF_HS);
        const float* W2s = (const float*)(sm + OFF_W2);
#pragma unroll
        for (int nb = 0; nb < 8; nb++) {
            int n0 = (ng * 8 + nb) * 8 + tig * 2;
            float4 wa = *(const float4*)&W2s[n0 * 4];
            float4 wb = *(const float4*)&W2s[n0 * 4 + 4];
            {
                float2 hc = *(const float2*)&Hsf[(mg * 2) * 128 + n0];
                float h00 = gelu_f(d0[nb][0] + hc.x), h01 = gelu_f(d0[nb][1] + hc.y);
                float h10 = gelu_f(d0[nb][2] + hc.x), h11 = gelu_f(d0[nb][3] + hc.y);
                LA0[0] += h00 * wa.x + h01 * wb.x; LA0[1] += h00 * wa.y + h01 * wb.y;
                LA0[2] += h00 * wa.z + h01 * wb.z; LA0[3] += h00 * wa.w + h01 * wb.w;
                LB0[0] += h10 * wa.x + h11 * wb.x; LB0[1] += h10 * wa.y + h11 * wb.y;
                LB0[2] += h10 * wa.z + h11 * wb.z; LB0[3] += h10 * wa.w + h11 * wb.w;
            }
            {
                float2 hc = *(const float2*)&Hsf[(mg * 2 + 1) * 128 + n0];
                float h00 = gelu_f(d1[nb][0] + hc.x), h01 = gelu_f(d1[nb][1] + hc.y);
                float h10 = gelu_f(d1[nb][2] + hc.x), h11 = gelu_f(d1[nb][3] + hc.y);
                LA1[0] += h00 * wa.x + h01 * wb.x; LA1[1] += h00 * wa.y + h01 * wb.y;
                LA1[2] += h00 * wa.z + h01 * wb.z; LA1[3] += h00 * wa.w + h01 * wb.w;
                LB1[0] += h10 * wa.x + h11 * wb.x; LB1[1] += h10 * wa.y + h11 * wb.y;
                LB1[2] += h10 * wa.z + h11 * wb.z; LB1[3] += h10 * wa.w + h11 * wb.w;
            }
        }
#pragma unroll
        for (int off = 1; off <= 2; off <<= 1) {
#pragma unroll
            for (int q = 0; q < 4; q++) {
                LA0[q] += __shfl_xor_sync(0xffffffffu, LA0[q], off);
                LB0[q] += __shfl_xor_sync(0xffffffffu, LB0[q], off);
                LA1[q] += __shfl_xor_sync(0xffffffffu, LA1[q], off);
                LB1[q] += __shfl_xor_sync(0xffffffffu, LB1[q], off);
            }
        }
        if (tig == 0) {
            float4* Ls = (float4*)(sm + OFF_LS);
            Ls[ng * 128 + (mg * 2) * 16 + gid]         = make_float4(LA0[0], LA0[1], LA0[2], LA0[3]);
            Ls[ng * 128 + (mg * 2) * 16 + gid + 8]     = make_float4(LB0[0], LB0[1], LB0[2], LB0[3]);
            Ls[ng * 128 + (mg * 2 + 1) * 16 + gid]     = make_float4(LA1[0], LA1[1], LA1[2], LA1[3]);
            Ls[ng * 128 + (mg * 2 + 1) * 16 + gid + 8] = make_float4(LB1[0], LB1[1], LB1[2], LB1[3]);
        }
        __syncthreads();
        if (tid < 128) {
            const float4* Ls = (const float4*)(sm + OFF_LS);
            float4 pa = Ls[tid], pb = Ls[128 + tid];
            float l0 = pa.x + pb.x + b2v.x, l1 = pa.y + pb.y + b2v.y;
            float l2 = pa.z + pb.z + b2v.z, l3 = pa.w + pb.w + b2v.w;
            float s0 = l0 * it_h, s1 = l1 * it_h, s2 = l2 * it_h, s3 = l3 * it_h;
            float m = fmaxf(fmaxf(s0, s1), fmaxf(s2, s3));
            float e0 = expf(s0 - m), e1 = expf(s1 - m);
            float e2 = expf(s2 - m), e3 = expf(s3 - m);
            float inv = 1.f / (e0 + e1 + e2 + e3);
            float w0 = fmaxf(e0 * inv, fl_h.x);
            float w1 = fmaxf(e1 * inv, fl_h.y);
            float w2_ = fmaxf(e2 * inv, fl_h.z);
            float w3 = fmaxf(e3 * inv, fl_h.w);
            float inv2 = 1.f / (w0 + w1 + w2_ + w3);
            int bl = tid >> 4, head = tid & 15;
            *(float4*)(out + (size_t)(base + bl) * 64 + head * 4) =
                make_float4(w0 * inv2, w1 * inv2, w2_ * inv2, w3 * inv2);
        }
        __syncthreads();
    }
}

// ---------------------------------------------------------------------------
extern "C" void kernel_launch(void* const* d_in, const int* in_sizes, int n_in,
                              void* d_out, int out_size) {
    (void)in_sizes; (void)n_in; (void)out_size;
    const float* hidden = (const float*)d_in[0];
    const float* b0     = (const float*)d_in[1];
    const float* b1br   = (const float*)d_in[2];
    const float* b2br   = (const float*)d_in[3];
    const float* b3br   = (const float*)d_in[4];
    const float* W1     = (const float*)d_in[5];
    const float* b1     = (const float*)d_in[6];
    const float* W2     = (const float*)d_in[7];
    const float* b2     = (const float*)d_in[8];
    const float* eps    = (const float*)d_in[9];
    const float* temp   = (const float*)d_in[10];
    float* out = (float*)d_out;

    cudaFuncSetAttribute(gate_mma, cudaFuncAttributeMaxDynamicSharedMemorySize,
                         (int)SM_TOT);

    prep_kernel<<<128, 256>>>(hidden, W1, b1);
    wt_kernel<<<33, 256>>>(W1);
    gate_mma<<<148, 256, SM_TOT>>>(b0, b1br, b2br, b3br, W2, b2, eps, temp, out);
}

// round 7
// speedup vs baseline: 4.6522x; 1.1810x over previous
#include <cuda_runtime.h>
#include <math.h>
#include <stdint.h>

#define NBL  4096
#define HIDD 1024
#define OUTC 128
typedef unsigned long long ull;
typedef uint32_t u32;

// ---------------- device scratch (allocation-free rule) ----------------
__device__ __align__(16) float g_Hc[NBL * OUTC];   // hidden @ W1[0:1024] + b1
__device__ __align__(16) float g_Wt[34 * 16 * 64]; // W in B-fragment layout (tf32)

// ---------------- helpers ----------------
__device__ __forceinline__ float gelu_f(float x) {
    return 0.5f * x * (1.0f + erff(x * 0.70710678118654752440f));
}
__device__ __forceinline__ u32 to_tf32(float x) {
    u32 o;
    asm("cvt.rna.tf32.f32 %0, %1;" : "=r"(o) : "f"(x));
    return o;
}
__device__ __forceinline__ void mma8(float& d0, float& d1, float& d2, float& d3,
                                     u32 a0, u32 a1, u32 a2, u32 a3,
                                     u32 b0, u32 b1) {
    asm volatile("mma.sync.aligned.m16n8k8.row.col.f32.tf32.tf32.f32 "
                 "{%0,%1,%2,%3}, {%4,%5,%6,%7}, {%8,%9}, {%0,%1,%2,%3};"
                 : "+f"(d0), "+f"(d1), "+f"(d2), "+f"(d3)
                 : "r"(a0), "r"(a1), "r"(a2), "r"(a3), "r"(b0), "r"(b1));
}

// ---------------------------------------------------------------------------
// prep_mma (blocks 0..127): g_Hc = hidden @ W1[0:1024] + b1 via tf32 mma.
//   CTA tile M=32, N=128, K streamed in 16 chunks of 64, double-buffered
//   fragment-layout smem. Warp (mg=warp&1, ng=warp>>1): M16 x N32.
// wt part (blocks 128..160): build gate W fragments in g_Wt (as before).
// ---------------------------------------------------------------------------
#define PREP_SMEM (20480 * 4)   // Af 2x2048 words + Bf 2x8192 words = 80KB

__global__ __launch_bounds__(256) void prep_mma(const float* __restrict__ A,
                                                const float* __restrict__ W1,
                                                const float* __restrict__ b1) {
    const int tid = threadIdx.x;

    if (blockIdx.x >= 128) {
        // ---- wt part: W fragments for the gate kernel ----
        u32* dst = (u32*)g_Wt;
        if (blockIdx.x < 160) {
            int kb = blockIdx.x - 128;
#pragma unroll
            for (int i = 0; i < 4; i++) {
                int gi = tid + i * 256;
                int nb = gi >> 6, rem = gi & 63, l = rem >> 1, w = rem & 1;
                int kabs = kb * 8 + (l & 3) + w * 4;
                int n = nb * 8 + (l >> 2);
                float v = W1[(size_t)(1792 + kabs) * 128 + n];
                dst[(kb * 16 + nb) * 64 + l * 2 + w] = to_tf32(v);
            }
        } else {
#pragma unroll 1
            for (int i = 0; i < 8; i++) {
                int gi = tid + i * 256;
                int kbs = gi >> 10, rem = gi & 1023;
                int nb = rem >> 6, rem2 = rem & 63, l = rem2 >> 1, w = rem2 & 1;
                int sk = kbs * 8 + (l & 3) + w * 4;
                int n = nb * 8 + (l >> 2);
                float v = 0.f;
                if (sk < 12) {
                    const float* p = W1 + (size_t)(1024 + sk * 64) * 128 + n;
#pragma unroll 8
                    for (int r = 0; r < 64; r++) v += p[(size_t)r * 128];
                }
                dst[((32 + kbs) * 16 + nb) * 64 + l * 2 + w] = to_tf32(v);
            }
        }
        return;
    }

    // ---- GEMM part ----
    extern __shared__ u32 smw[];
    u32* Af = smw;          // [2][2048]
    u32* Bf = smw + 4096;   // [2][8192]

    const int m0 = blockIdx.x * 32;
    const int lane = tid & 31, warp = tid >> 5;
    const int mg = warp & 1, ng = warp >> 1;        // mg 0..1, ng 0..3

    // A-writer constants: thread t -> row ar, k-block akb, 8 k-values
    const int ar = tid >> 3, akb = tid & 7;
    const int arl = ar & 7, arh = ((ar & 15) >= 8) ? 1 : 0;
    const int afrag = akb * 2 + (ar >> 4);
    const u32 aswz = (u32)((arl << 2) ^ (akb << 2));
    const float* Ag = A + (size_t)(m0 + ar) * HIDD + akb * 8;

    // B-writer constants: thread t -> k-row bk, 32 n-values from bn0
    const int bk = tid >> 2, bn0 = (tid & 3) * 32;
    const int bkb = bk >> 3, bkl = bk & 7;
    const int bw = (bkl >= 4) ? 1 : 0, bkq = bkl & 3;
    const float* Bg = W1 + (size_t)bk * OUTC + bn0;

    // reader constants
    const u32 ard = (u32)((lane * 4) ^ ((lane >> 2) << 2));

    float d[4][4];
#pragma unroll
    for (int i = 0; i < 4; i++)
#pragma unroll
        for (int j = 0; j < 4; j++) d[i][j] = 0.f;

    float av[8];
    float bv[32];

#define LDGA(CK) do {                                                  \
    float4 t0 = *(const float4*)(Ag + (CK) * 64);                      \
    float4 t1 = *(const float4*)(Ag + (CK) * 64 + 4);                  \
    av[0]=t0.x; av[1]=t0.y; av[2]=t0.z; av[3]=t0.w;                    \
    av[4]=t1.x; av[5]=t1.y; av[6]=t1.z; av[7]=t1.w;                    \
} while (0)

#define LDGB(CK) do {                                                  \
    _Pragma("unroll")                                                  \
    for (int g_ = 0; g_ < 8; g_++) {                                   \
        float4 t_ = *(const float4*)(Bg + (size_t)(CK) * 64 * OUTC + g_ * 4); \
        bv[g_*4+0]=t_.x; bv[g_*4+1]=t_.y; bv[g_*4+2]=t_.z; bv[g_*4+3]=t_.w;  \
    }                                                                  \
} while (0)

#define STORE(BUF) do {                                                \
    _Pragma("unroll")                                                  \
    for (int j_ = 0; j_ < 8; j_++) {                                   \
        u32 wi_ = (u32)(arl * 16 + (j_ & 3) * 4 + arh + ((j_ >= 4) ? 2 : 0)) ^ aswz; \
        Af[(BUF) * 2048 + afrag * 128 + wi_] = to_tf32(av[j_]);        \
    }                                                                  \
    _Pragma("unroll")                                                  \
    for (int j_ = 0; j_ < 32; j_++) {                                  \
        int n_ = bn0 + j_;                                             \
        int nb_ = n_ >> 3;                                             \
        u32 x_ = (u32)((((n_ & 7) * 4 + bkq) * 2 + bw)) ^ (u32)(nb_ << 1); \
        Bf[(BUF) * 8192 + (bkb * 16 + nb_) * 64 + x_] = to_tf32(bv[j_]); \
    }                                                                  \
} while (0)

#define MMACHUNK(BUF) do {                                             \
    _Pragma("unroll")                                                  \
    for (int kb_ = 0; kb_ < 8; kb_++) {                                \
        uint4 Av_ = *(const uint4*)&Af[(BUF) * 2048 + (kb_ * 2 + mg) * 128 \
                                       + (ard ^ (u32)(kb_ << 2))];     \
        _Pragma("unroll")                                              \
        for (int q_ = 0; q_ < 4; q_++) {                               \
            int nb_ = ng * 4 + q_;                                     \
            uint2 Bv_ = *(const uint2*)&Bf[(BUF) * 8192 + (kb_ * 16 + nb_) * 64 \
                                           + (u32)((lane * 2) ^ (nb_ << 1))];   \
            mma8(d[q_][0], d[q_][1], d[q_][2], d[q_][3],               \
                 Av_.x, Av_.y, Av_.z, Av_.w, Bv_.x, Bv_.y);            \
        }                                                              \
    }                                                                  \
} while (0)

    LDGA(0); LDGB(0);
    STORE(0);
    __syncthreads();

#pragma unroll 1
    for (int ck = 0; ck < 16; ck++) {
        if (ck < 15) { LDGA(ck + 1); LDGB(ck + 1); }
        MMACHUNK(ck & 1);
        if (ck < 15) {
            __syncthreads();        // all mma reads of buf (ck+1)&1 (from ck-1) done
            STORE((ck + 1) & 1);
            __syncthreads();
        }
    }

    // epilogue: add b1, write g_Hc
    const int row0 = m0 + mg * 16 + (lane >> 2);
    const int col0 = ng * 32 + (lane & 3) * 2;
#pragma unroll
    for (int q = 0; q < 4; q++) {
        int col = col0 + q * 8;
        float2 bb = *(const float2*)(b1 + col);
        *(float2*)&g_Hc[(size_t)row0 * OUTC + col] =
            make_float2(d[q][0] + bb.x, d[q][1] + bb.y);
        *(float2*)&g_Hc[(size_t)(row0 + 8) * OUTC + col] =
            make_float2(d[q][2] + bb.x, d[q][3] + bb.y);
    }
}

// ---------------------------------------------------------------------------
// gate_mma: persistent tf32 mma.sync gate kernel (unchanged from R6 pass).
// ---------------------------------------------------------------------------
#define OFF_W  0u
#define OFF_X  139264u
#define OFF_XS 204800u
#define OFF_HS 212992u
#define OFF_LS 217088u
#define OFF_W2 221184u
#define SM_TOT 223232u

__global__ __launch_bounds__(256, 1) void gate_mma(
    const float* __restrict__ br0, const float* __restrict__ br1,
    const float* __restrict__ br2, const float* __restrict__ br3,
    const float* __restrict__ W2,  const float* __restrict__ b2,
    const float* __restrict__ eps, const float* __restrict__ temp,
    float* __restrict__ out)
{
    extern __shared__ char sm[];
    const int tid  = threadIdx.x;
    const int lane = tid & 31, warp = tid >> 5;
    const int mg = warp >> 1, ng = warp & 1;

    {
        const float4* s = (const float4*)g_Wt;
        float4* d = (float4*)(sm + OFF_W);
        for (int i = tid; i < 8704; i += 256) d[i] = s[i];
    }
    {
        float4* d = (float4*)(sm + OFF_XS);
        for (int i = tid; i < 512; i += 256) d[i] = make_float4(0.f, 0.f, 0.f, 0.f);
    }
    {
        float* d = (float*)(sm + OFF_W2);
        for (int i = tid; i < 512; i += 256) d[i] = W2[i];
    }
    const float4 b2v = *(const float4*)b2;
    float it_h = 1.f;
    float4 fl_h = make_float4(0.f, 0.f, 0.f, 0.f);
    if (tid < 128) {
        int head = tid & 15;
        it_h = 1.f / fminf(fmaxf(temp[head], 0.2f), 10.0f);
        float4 ef = *(const float4*)(eps + head * 4);
        fl_h.x = fminf(fmaxf(ef.x, 1e-7f), 0.1f);
        fl_h.y = fminf(fmaxf(ef.y, 1e-7f), 0.1f);
        fl_h.z = fminf(fmaxf(ef.z, 1e-7f), 0.1f);
        fl_h.w = fminf(fmaxf(ef.w, 1e-7f), 0.1f);
    }
    __syncthreads();

    const int lm = tid >> 1, half = tid & 1;
    const int lmt = lm >> 4;
    const int lr  = lm & 15;
    const int rlow = lr & 7, rhi = (lr >= 8) ? 1 : 0;
    const int swzr = rlow << 2;
    const int swz_l = (lane * 4) ^ ((lane >> 2) << 2);
    const int tig = lane & 3, gid = lane >> 2;

    float4 v[8];
    int tt = blockIdx.x;
    {
        const float* src = br0 + (size_t)(tt * 8 + lmt) * 1024 + lr * 64 + half * 32;
#pragma unroll
        for (int j = 0; j < 8; j++) v[j] = *(const float4*)(src + j * 4);
    }

    for (; tt < 512; tt += 148) {
        const int base = tt * 8;

        {
            const float4* s = (const float4*)(g_Hc + (size_t)base * 128);
            ((float4*)(sm + OFF_HS))[tid] = s[tid];
        }

        float d0[8][4], d1[8][4];
#pragma unroll
        for (int nb = 0; nb < 8; nb++)
#pragma unroll
            for (int c = 0; c < 4; c++) { d0[nb][c] = 0.f; d1[nb][c] = 0.f; }

#pragma unroll 1
        for (int p = 0; p < 4; p++) {
            float s = 0.f, q2 = 0.f, mx = -INFINITY;
#pragma unroll
            for (int j = 0; j < 8; j++) {
                s  += (v[j].x + v[j].y) + (v[j].z + v[j].w);
                q2 += v[j].x * v[j].x + v[j].y * v[j].y
                    + v[j].z * v[j].z + v[j].w * v[j].w;
                mx = fmaxf(mx, fmaxf(fmaxf(v[j].x, v[j].y), fmaxf(v[j].z, v[j].w)));
            }
            s  += __shfl_xor_sync(0xffffffffu, s, 1);
            q2 += __shfl_xor_sync(0xffffffffu, q2, 1);
            mx  = fmaxf(mx, __shfl_xor_sync(0xffffffffu, mx, 1));

            {
                u32* xb = (u32*)(sm + OFF_X) + (p & 1) * 8192 + lmt * 1024;
                const float* vf = (const float*)v;
#pragma unroll
                for (int j = 0; j < 32; j++) {
                    int kbl = half * 4 + (j >> 3);
                    int off = (rlow * 16 + (j & 3) * 4 + rhi + (((j & 7) >= 4) ? 2 : 0)) ^ swzr;
                    xb[kbl * 128 + off] = to_tf32(vf[j]);
                }
                if (!half) {
                    float st0 = s * (1.f / 64.f);
                    float st1 = sqrtf(fmaxf(q2 * (1.f / 64.f), 1e-8f));
                    float st2 = mx;
                    u32* xs = (u32*)(sm + OFF_XS) + lmt * 256;
#pragma unroll
                    for (int t2 = 0; t2 < 3; t2++) {
                        int sk = p * 3 + t2;
                        int kbs = sk >> 3, kp = sk & 7;
                        int off = (rlow * 16 + (kp & 3) * 4 + rhi + ((kp >= 4) ? 2 : 0)) ^ swzr;
                        float sv = (t2 == 0) ? st0 : (t2 == 1) ? st1 : st2;
                        xs[kbs * 128 + off] = to_tf32(sv);
                    }
                }
            }
            __syncthreads();

            if (p < 3) {
                const float* bp = (p == 0) ? br1 : (p == 1) ? br2 : br3;
                const float* src = bp + (size_t)(base + lmt) * 1024 + lr * 64 + half * 32;
#pragma unroll
                for (int j = 0; j < 8; j++) v[j] = *(const float4*)(src + j * 4);
            }

            {
                const char* xbase  = sm + OFF_X + (p & 1) * 32768u;
                const char* abase0 = xbase + (mg * 2) * 4096 + swz_l * 4;
                const char* abase1 = xbase + (mg * 2 + 1) * 4096 + swz_l * 4;
                const char* wbase  = sm + OFF_W + (u32)((p * 8 * 16 + ng * 8) * 256) + lane * 8;
#pragma unroll 2
                for (int kbl = 0; kbl < 8; kbl++) {
                    uint4 A0 = *(const uint4*)(abase0 + kbl * 512);
                    uint4 A1 = *(const uint4*)(abase1 + kbl * 512);
                    const char* wk = wbase + kbl * 4096;
#pragma unroll
                    for (int nb = 0; nb < 8; nb++) {
                        uint2 B = *(const uint2*)(wk + nb * 256);
                        mma8(d0[nb][0], d0[nb][1], d0[nb][2], d0[nb][3],
                             A0.x, A0.y, A0.z, A0.w, B.x, B.y);
                        mma8(d1[nb][0], d1[nb][1], d1[nb][2], d1[nb][3],
                             A1.x, A1.y, A1.z, A1.w, B.x, B.y);
                    }
                }
                if (p == 3) {
                    const char* sbase0 = sm + OFF_XS + (mg * 2) * 1024 + swz_l * 4;
                    const char* sbase1 = sm + OFF_XS + (mg * 2 + 1) * 1024 + swz_l * 4;
#pragma unroll
                    for (int kbs = 0; kbs < 2; kbs++) {
                        uint4 A0 = *(const uint4*)(sbase0 + kbs * 512);
                        uint4 A1 = *(const uint4*)(sbase1 + kbs * 512);
                        const char* wk = sm + OFF_W
                                       + (u32)(((32 + kbs) * 16 + ng * 8) * 256) + lane * 8;
#pragma unroll
                        for (int nb = 0; nb < 8; nb++) {
                            uint2 B = *(const uint2*)(wk + nb * 256);
                            mma8(d0[nb][0], d0[nb][1], d0[nb][2], d0[nb][3],
                                 A0.x, A0.y, A0.z, A0.w, B.x, B.y);
                            mma8(d1[nb][0], d1[nb][1], d1[nb][2], d1[nb][3],
                                 A1.x, A1.y, A1.z, A1.w, B.x, B.y);
                        }
                    }
                }
            }
        } // p loop

        if (tt + 148 < 512) {
            const float* src = br0 + (size_t)((tt + 148) * 8 + lmt) * 1024
                             + lr * 64 + half * 32;
#pragma unroll
            for (int j = 0; j < 8; j++) v[j] = *(const float4*)(src + j * 4);
        }

        float LA0[4] = {0.f, 0.f, 0.f, 0.f}, LB0[4] = {0.f, 0.f, 0.f, 0.f};
        float LA1[4] = {0.f, 0.f, 0.f, 0.f}, LB1[4] = {0.f, 0.f, 0.f, 0.f};
        const float* Hsf = (const float*)(sm + OFF_HS);
        const float* W2s = (const float*)(sm + OFF_W2);
#pragma unroll
        for (int nb = 0; nb < 8; nb++) {
            int n0 = (ng * 8 + nb) * 8 + tig * 2;
            float4 wa = *(const float4*)&W2s[n0 * 4];
            float4 wb = *(const float4*)&W2s[n0 * 4 + 4];
            {
                float2 hc = *(const float2*)&Hsf[(mg * 2) * 128 + n0];
                float h00 = gelu_f(d0[nb][0] + hc.x), h01 = gelu_f(d0[nb][1] + hc.y);
                float h10 = gelu_f(d0[nb][2] + hc.x), h11 = gelu_f(d0[nb][3] + hc.y);
                LA0[0] += h00 * wa.x + h01 * wb.x; LA0[1] += h00 * wa.y + h01 * wb.y;
                LA0[2] += h00 * wa.z + h01 * wb.z; LA0[3] += h00 * wa.w + h01 * wb.w;
                LB0[0] += h10 * wa.x + h11 * wb.x; LB0[1] += h10 * wa.y + h11 * wb.y;
                LB0[2] += h10 * wa.z + h11 * wb.z; LB0[3] += h10 * wa.w + h11 * wb.w;
            }
            {
                float2 hc = *(const float2*)&Hsf[(mg * 2 + 1) * 128 + n0];
                float h00 = gelu_f(d1[nb][0] + hc.x), h01 = gelu_f(d1[nb][1] + hc.y);
                float h10 = gelu_f(d1[nb][2] + hc.x), h11 = gelu_f(d1[nb][3] + hc.y);
                LA1[0] += h00 * wa.x + h01 * wb.x; LA1[1] += h00 * wa.y + h01 * wb.y;
                LA1[2] += h00 * wa.z + h01 * wb.z; LA1[3] += h00 * wa.w + h01 * wb.w;
                LB1[0] += h10 * wa.x + h11 * wb.x; LB1[1] += h10 * wa.y + h11 * wb.y;
                LB1[2] += h10 * wa.z + h11 * wb.z; LB1[3] += h10 * wa.w + h11 * wb.w;
            }
        }
#pragma unroll
        for (int off = 1; off <= 2; off <<= 1) {
#pragma unroll
            for (int q = 0; q < 4; q++) {
                LA0[q] += __shfl_xor_sync(0xffffffffu, LA0[q], off);
                LB0[q] += __shfl_xor_sync(0xffffffffu, LB0[q], off);
                LA1[q] += __shfl_xor_sync(0xffffffffu, LA1[q], off);
                LB1[q] += __shfl_xor_sync(0xffffffffu, LB1[q], off);
            }
        }
        if (tig == 0) {
            float4* Ls = (float4*)(sm + OFF_LS);
            Ls[ng * 128 + (mg * 2) * 16 + gid]         = make_float4(LA0[0], LA0[1], LA0[2], LA0[3]);
            Ls[ng * 128 + (mg * 2) * 16 + gid + 8]     = make_float4(LB0[0], LB0[1], LB0[2], LB0[3]);
            Ls[ng * 128 + (mg * 2 + 1) * 16 + gid]     = make_float4(LA1[0], LA1[1], LA1[2], LA1[3]);
            Ls[ng * 128 + (mg * 2 + 1) * 16 + gid + 8] = make_float4(LB1[0], LB1[1], LB1[2], LB1[3]);
        }
        __syncthreads();
        if (tid < 128) {
            const float4* Ls = (const float4*)(sm + OFF_LS);
            float4 pa = Ls[tid], pb = Ls[128 + tid];
            float l0 = pa.x + pb.x + b2v.x, l1 = pa.y + pb.y + b2v.y;
            float l2 = pa.z + pb.z + b2v.z, l3 = pa.w + pb.w + b2v.w;
            float s0 = l0 * it_h, s1 = l1 * it_h, s2 = l2 * it_h, s3 = l3 * it_h;
            float m = fmaxf(fmaxf(s0, s1), fmaxf(s2, s3));
            float e0 = expf(s0 - m), e1 = expf(s1 - m);
            float e2 = expf(s2 - m), e3 = expf(s3 - m);
            float inv = 1.f / (e0 + e1 + e2 + e3);
            float w0 = fmaxf(e0 * inv, fl_h.x);
            float w1 = fmaxf(e1 * inv, fl_h.y);
            float w2_ = fmaxf(e2 * inv, fl_h.z);
            float w3 = fmaxf(e3 * inv, fl_h.w);
            float inv2 = 1.f / (w0 + w1 + w2_ + w3);
            int bl = tid >> 4, head = tid & 15;
            *(float4*)(out + (size_t)(base + bl) * 64 + head * 4) =
                make_float4(w0 * inv2, w1 * inv2, w2_ * inv2, w3 * inv2);
        }
        __syncthreads();
    }
}

// ---------------------------------------------------------------------------
extern "C" void kernel_launch(void* const* d_in, const int* in_sizes, int n_in,
                              void* d_out, int out_size) {
    (void)in_sizes; (void)n_in; (void)out_size;
    const float* hidden = (const float*)d_in[0];
    const float* b0     = (const float*)d_in[1];
    const float* b1br   = (const float*)d_in[2];
    const float* b2br   = (const float*)d_in[3];
    const float* b3br   = (const float*)d_in[4];
    const float* W1     = (const float*)d_in[5];
    const float* b1     = (const float*)d_in[6];
    const float* W2     = (const float*)d_in[7];
    const float* b2     = (const float*)d_in[8];
    const float* eps    = (const float*)d_in[9];
    const float* temp   = (const float*)d_in[10];
    float* out = (float*)d_out;

    cudaFuncSetAttribute(prep_mma, cudaFuncAttributeMaxDynamicSharedMemorySize,
                         (int)PREP_SMEM);
    cudaFuncSetAttribute(gate_mma, cudaFuncAttributeMaxDynamicSharedMemorySize,
                         (int)SM_TOT);

    prep_mma<<<161, 256, PREP_SMEM>>>(hidden, W1, b1);
    gate_mma<<<148, 256, SM_TOT>>>(b0, b1br, b2br, b3br, W2, b2, eps, temp, out);
}

// round 8
// speedup vs baseline: 5.6944x; 1.2240x over previous
#include <cuda_runtime.h>
#include <math.h>
#include <stdint.h>

#define NBL  4096
#define HIDD 1024
#define OUTC 128
typedef unsigned long long ull;
typedef uint32_t u32;

// ---------------- device scratch (allocation-free rule) ----------------
__device__ __align__(16) float g_Hc[NBL * OUTC];   // hidden @ W1[0:1024] + b1
__device__ __align__(16) float g_Wt[34 * 16 * 64]; // W in B-fragment layout (tf32)

// ---------------- helpers ----------------
__device__ __forceinline__ float gelu_f(float x) {
    return 0.5f * x * (1.0f + erff(x * 0.70710678118654752440f));
}
__device__ __forceinline__ u32 to_tf32(float x) {
    u32 o;
    asm("cvt.rna.tf32.f32 %0, %1;" : "=r"(o) : "f"(x));
    return o;
}
__device__ __forceinline__ void mma8(float& d0, float& d1, float& d2, float& d3,
                                     u32 a0, u32 a1, u32 a2, u32 a3,
                                     u32 b0, u32 b1) {
    asm volatile("mma.sync.aligned.m16n8k8.row.col.f32.tf32.tf32.f32 "
                 "{%0,%1,%2,%3}, {%4,%5,%6,%7}, {%8,%9}, {%0,%1,%2,%3};"
                 : "+f"(d0), "+f"(d1), "+f"(d2), "+f"(d3)
                 : "r"(a0), "r"(a1), "r"(a2), "r"(a3), "r"(b0), "r"(b1));
}

// ---------------------------------------------------------------------------
// prep_mma:
//  blocks 0..127   : g_Hc = hidden @ W1[0:1024] + b1 (tf32 mma, M=32 tile)
//  blocks 128..159 : branch W fragments (kb = bid-128)
//  blocks 160..171 : stat-row s = bid-160 fragment (parallel column sums)
//  block  172      : zero-pad fragments for sk 12..15
// ---------------------------------------------------------------------------
#define PREP_SMEM (20480 * 4)

__global__ __launch_bounds__(256) void prep_mma(const float* __restrict__ A,
                                                const float* __restrict__ W1,
                                                const float* __restrict__ b1) {
    const int tid = threadIdx.x;

    if (blockIdx.x >= 128) {
        u32* dst = (u32*)g_Wt;
        if (blockIdx.x < 160) {
            int kb = blockIdx.x - 128;
#pragma unroll
            for (int i = 0; i < 4; i++) {
                int gi = tid + i * 256;
                int nb = gi >> 6, rem = gi & 63, l = rem >> 1, w = rem & 1;
                int kabs = kb * 8 + (l & 3) + w * 4;
                int n = nb * 8 + (l >> 2);
                float v = W1[(size_t)(1792 + kabs) * 128 + n];
                dst[(kb * 16 + nb) * 64 + l * 2 + w] = to_tf32(v);
            }
        } else if (blockIdx.x < 172) {
            // parallel stat-row sum: s fixed, thread = (n, half)
            int s = blockIdx.x - 160;
            int n = tid >> 1, half = tid & 1;
            const float* p = W1 + (size_t)(1024 + s * 64 + half * 32) * 128 + n;
            float acc = 0.f;
#pragma unroll 8
            for (int r = 0; r < 32; r++) acc += p[(size_t)r * 128];
            acc += __shfl_xor_sync(0xffffffffu, acc, 1);
            if (!half) {
                int kbs = s >> 3;
                int w = ((s & 7) >= 4) ? 1 : 0;
                int lpos = (s & 3) + ((n & 7) << 2);
                int nb = n >> 3;
                dst[((32 + kbs) * 16 + nb) * 64 + lpos * 2 + w] = to_tf32(acc);
            }
        } else {
            // zero pads: sk 12..15 (kbs=1, w=1)
#pragma unroll
            for (int i = 0; i < 2; i++) {
                int idx = tid + i * 256;          // 0..511
                int sk = 12 + (idx >> 7), n = idx & 127;
                int lpos = (sk & 3) + ((n & 7) << 2);
                int nb = n >> 3;
                dst[((32 + 1) * 16 + nb) * 64 + lpos * 2 + 1] = 0u;
            }
        }
        return;
    }

    // ---- GEMM part ----
    extern __shared__ u32 smw[];
    u32* Af = smw;          // [2][2048]
    u32* Bf = smw + 4096;   // [2][8192]

    const int m0 = blockIdx.x * 32;
    const int lane = tid & 31, warp = tid >> 5;
    const int mg = warp & 1, ng = warp >> 1;

    const int ar = tid >> 3, akb = tid & 7;
    const int arl = ar & 7, arh = ((ar & 15) >= 8) ? 1 : 0;
    const int afrag = akb * 2 + (ar >> 4);
    const u32 aswz = (u32)((arl << 2) ^ (akb << 2));
    const float* Ag = A + (size_t)(m0 + ar) * HIDD + akb * 8;

    const int bk = tid >> 2, bn0 = (tid & 3) * 32;
    const int bkb = bk >> 3, bkl = bk & 7;
    const int bw = (bkl >= 4) ? 1 : 0, bkq = bkl & 3;
    const float* Bg = W1 + (size_t)bk * OUTC + bn0;

    const u32 ard = (u32)((lane * 4) ^ ((lane >> 2) << 2));

    float d[4][4];
#pragma unroll
    for (int i = 0; i < 4; i++)
#pragma unroll
        for (int j = 0; j < 4; j++) d[i][j] = 0.f;

    float av[8];
    float bv[32];

#define LDGA(CK) do {                                                  \
    float4 t0 = *(const float4*)(Ag + (CK) * 64);                      \
    float4 t1 = *(const float4*)(Ag + (CK) * 64 + 4);                  \
    av[0]=t0.x; av[1]=t0.y; av[2]=t0.z; av[3]=t0.w;                    \
    av[4]=t1.x; av[5]=t1.y; av[6]=t1.z; av[7]=t1.w;                    \
} while (0)

#define LDGB(CK) do {                                                  \
    _Pragma("unroll")                                                  \
    for (int g_ = 0; g_ < 8; g_++) {                                   \
        float4 t_ = *(const float4*)(Bg + (size_t)(CK) * 64 * OUTC + g_ * 4); \
        bv[g_*4+0]=t_.x; bv[g_*4+1]=t_.y; bv[g_*4+2]=t_.z; bv[g_*4+3]=t_.w;  \
    }                                                                  \
} while (0)

#define STORE(BUF) do {                                                \
    _Pragma("unroll")                                                  \
    for (int j_ = 0; j_ < 8; j_++) {                                   \
        u32 wi_ = (u32)(arl * 16 + (j_ & 3) * 4 + arh + ((j_ >= 4) ? 2 : 0)) ^ aswz; \
        Af[(BUF) * 2048 + afrag * 128 + wi_] = to_tf32(av[j_]);        \
    }                                                                  \
    _Pragma("unroll")                                                  \
    for (int j_ = 0; j_ < 32; j_++) {                                  \
        int n_ = bn0 + j_;                                             \
        int nb_ = n_ >> 3;                                             \
        u32 x_ = (u32)((((n_ & 7) * 4 + bkq) * 2 + bw)) ^ (u32)(nb_ << 1); \
        Bf[(BUF) * 8192 + (bkb * 16 + nb_) * 64 + x_] = to_tf32(bv[j_]); \
    }                                                                  \
} while (0)

#define MMACHUNK(BUF) do {                                             \
    _Pragma("unroll")                                                  \
    for (int kb_ = 0; kb_ < 8; kb_++) {                                \
        uint4 Av_ = *(const uint4*)&Af[(BUF) * 2048 + (kb_ * 2 + mg) * 128 \
                                       + (ard ^ (u32)(kb_ << 2))];     \
        _Pragma("unroll")                                              \
        for (int q_ = 0; q_ < 4; q_++) {                               \
            int nb_ = ng * 4 + q_;                                     \
            uint2 Bv_ = *(const uint2*)&Bf[(BUF) * 8192 + (kb_ * 16 + nb_) * 64 \
                                           + (u32)((lane * 2) ^ (nb_ << 1))];   \
            mma8(d[q_][0], d[q_][1], d[q_][2], d[q_][3],               \
                 Av_.x, Av_.y, Av_.z, Av_.w, Bv_.x, Bv_.y);            \
        }                                                              \
    }                                                                  \
} while (0)

    LDGA(0); LDGB(0);
    STORE(0);
    __syncthreads();

#pragma unroll 1
    for (int ck = 0; ck < 16; ck++) {
        if (ck < 15) { LDGA(ck + 1); LDGB(ck + 1); }
        MMACHUNK(ck & 1);
        if (ck < 15) {
            __syncthreads();
            STORE((ck + 1) & 1);
            __syncthreads();
        }
    }

    const int row0 = m0 + mg * 16 + (lane >> 2);
    const int col0 = ng * 32 + (lane & 3) * 2;
#pragma unroll
    for (int q = 0; q < 4; q++) {
        int col = col0 + q * 8;
        float2 bb = *(const float2*)(b1 + col);
        *(float2*)&g_Hc[(size_t)row0 * OUTC + col] =
            make_float2(d[q][0] + bb.x, d[q][1] + bb.y);
        *(float2*)&g_Hc[(size_t)(row0 + 8) * OUTC + col] =
            make_float2(d[q][2] + bb.x, d[q][3] + bb.y);
    }
}

// ---------------------------------------------------------------------------
// gate_mma: persistent tf32 mma gate kernel, now 512 threads (16 warps).
// Tile M=128 (8 bl x 16 heads), N=128, K=272.
// Warp (mg=warp>>1 -> mtile 0..7, ng=warp&1 -> N half): M16 x N64, 32 accs.
// Loader: thread t -> row lm=t>>2, quarter q=t&3 (16 floats).
// ---------------------------------------------------------------------------
#define OFF_W  0u
#define OFF_X  139264u
#define OFF_XS 204800u
#define OFF_HS 212992u
#define OFF_LS 217088u
#define OFF_W2 221184u
#define SM_TOT 223232u

__global__ __launch_bounds__(512, 1) void gate_mma(
    const float* __restrict__ br0, const float* __restrict__ br1,
    const float* __restrict__ br2, const float* __restrict__ br3,
    const float* __restrict__ W2,  const float* __restrict__ b2,
    const float* __restrict__ eps, const float* __restrict__ temp,
    float* __restrict__ out)
{
    extern __shared__ char sm[];
    const int tid  = threadIdx.x;
    const int lane = tid & 31, warp = tid >> 5;
    const int mg = warp >> 1, ng = warp & 1;   // mg 0..7 (mtile), ng 0..1

    {
        const float4* s = (const float4*)g_Wt;
        float4* d = (float4*)(sm + OFF_W);
        for (int i = tid; i < 8704; i += 512) d[i] = s[i];
    }
    {
        float4* d = (float4*)(sm + OFF_XS);
        for (int i = tid; i < 512; i += 512) d[i] = make_float4(0.f, 0.f, 0.f, 0.f);
    }
    {
        float* d = (float*)(sm + OFF_W2);
        if (tid < 512) d[tid] = W2[tid];
    }
    const float4 b2v = *(const float4*)b2;
    float it_h = 1.f;
    float4 fl_h = make_float4(0.f, 0.f, 0.f, 0.f);
    if (tid < 128) {
        int head = tid & 15;
        it_h = 1.f / fminf(fmaxf(temp[head], 0.2f), 10.0f);
        float4 ef = *(const float4*)(eps + head * 4);
        fl_h.x = fminf(fmaxf(ef.x, 1e-7f), 0.1f);
        fl_h.y = fminf(fmaxf(ef.y, 1e-7f), 0.1f);
        fl_h.z = fminf(fmaxf(ef.z, 1e-7f), 0.1f);
        fl_h.w = fminf(fmaxf(ef.w, 1e-7f), 0.1f);
    }
    __syncthreads();

    // loader constants: row lm = tid>>2, quarter q = tid&3 (k in [q*16, q*16+16))
    const int lm = tid >> 2, lq = tid & 3;
    const int lmt = lm >> 4;          // bl in tile (mtile)
    const int lr  = lm & 15;          // head
    const int rlow = lr & 7, rhi = (lr >= 8) ? 1 : 0;
    const int swzr = rlow << 2;
    const int swz_l = (lane * 4) ^ ((lane >> 2) << 2);
    const int tig = lane & 3, gid = lane >> 2;

    float4 v[4];
    int tt = blockIdx.x;
    {
        const float* src = br0 + (size_t)(tt * 8 + lmt) * 1024 + lr * 64 + lq * 16;
#pragma unroll
        for (int j = 0; j < 4; j++) v[j] = *(const float4*)(src + j * 4);
    }

    for (; tt < 512; tt += 148) {
        const int base = tt * 8;

        if (tid < 256) {
            const float4* s = (const float4*)(g_Hc + (size_t)base * 128);
            ((float4*)(sm + OFF_HS))[tid] = s[tid];
        }

        float d[8][4];
#pragma unroll
        for (int nb = 0; nb < 8; nb++)
#pragma unroll
            for (int c = 0; c < 4; c++) d[nb][c] = 0.f;

#pragma unroll 1
        for (int p = 0; p < 4; p++) {
            float s = 0.f, q2 = 0.f, mx = -INFINITY;
#pragma unroll
            for (int j = 0; j < 4; j++) {
                s  += (v[j].x + v[j].y) + (v[j].z + v[j].w);
                q2 += v[j].x * v[j].x + v[j].y * v[j].y
                    + v[j].z * v[j].z + v[j].w * v[j].w;
                mx = fmaxf(mx, fmaxf(fmaxf(v[j].x, v[j].y), fmaxf(v[j].z, v[j].w)));
            }
            s  += __shfl_xor_sync(0xffffffffu, s, 1);
            q2 += __shfl_xor_sync(0xffffffffu, q2, 1);
            mx  = fmaxf(mx, __shfl_xor_sync(0xffffffffu, mx, 1));
            s  += __shfl_xor_sync(0xffffffffu, s, 2);
            q2 += __shfl_xor_sync(0xffffffffu, q2, 2);
            mx  = fmaxf(mx, __shfl_xor_sync(0xffffffffu, mx, 2));

            {
                u32* xb = (u32*)(sm + OFF_X) + (p & 1) * 8192 + lmt * 1024;
                const float* vf = (const float*)v;
#pragma unroll
                for (int j = 0; j < 16; j++) {
                    int kbl = lq * 2 + (j >> 3);
                    int kp  = j & 7;
                    int off = (rlow * 16 + (kp & 3) * 4 + rhi + ((kp >= 4) ? 2 : 0)) ^ swzr;
                    xb[kbl * 128 + off] = to_tf32(vf[j]);
                }
                if (lq == 0) {
                    float st0 = s * (1.f / 64.f);
                    float st1 = sqrtf(fmaxf(q2 * (1.f / 64.f), 1e-8f));
                    float st2 = mx;
                    u32* xs = (u32*)(sm + OFF_XS) + lmt * 256;
#pragma unroll
                    for (int t2 = 0; t2 < 3; t2++) {
                        int sk = p * 3 + t2;
                        int kbs = sk >> 3, kp = sk & 7;
                        int off = (rlow * 16 + (kp & 3) * 4 + rhi + ((kp >= 4) ? 2 : 0)) ^ swzr;
                        float sv = (t2 == 0) ? st0 : (t2 == 1) ? st1 : st2;
                        xs[kbs * 128 + off] = to_tf32(sv);
                    }
                }
            }
            __syncthreads();

            if (p < 3) {
                const float* bp = (p == 0) ? br1 : (p == 1) ? br2 : br3;
                const float* src = bp + (size_t)(base + lmt) * 1024 + lr * 64 + lq * 16;
#pragma unroll
                for (int j = 0; j < 4; j++) v[j] = *(const float4*)(src + j * 4);
            }

            {
                const char* xbase = sm + OFF_X + (p & 1) * 32768u;
                const char* abase = xbase + mg * 4096 + swz_l * 4;
                const char* wbase = sm + OFF_W + (u32)((p * 128 + ng * 8) * 256) + lane * 8;
#pragma unroll 2
                for (int kbl = 0; kbl < 8; kbl++) {
                    uint4 A0 = *(const uint4*)(abase + kbl * 512);
                    const char* wk = wbase + kbl * 4096;
#pragma unroll
                    for (int nb = 0; nb < 8; nb++) {
                        uint2 B = *(const uint2*)(wk + nb * 256);
                        mma8(d[nb][0], d[nb][1], d[nb][2], d[nb][3],
                             A0.x, A0.y, A0.z, A0.w, B.x, B.y);
                    }
                }
                if (p == 3) {
                    const char* sbase = sm + OFF_XS + mg * 1024 + swz_l * 4;
#pragma unroll
                    for (int kbs = 0; kbs < 2; kbs++) {
                        uint4 A0 = *(const uint4*)(sbase + kbs * 512);
                        const char* wk = sm + OFF_W
                                       + (u32)(((32 + kbs) * 16 + ng * 8) * 256) + lane * 8;
#pragma unroll
                        for (int nb = 0; nb < 8; nb++) {
                            uint2 B = *(const uint2*)(wk + nb * 256);
                            mma8(d[nb][0], d[nb][1], d[nb][2], d[nb][3],
                                 A0.x, A0.y, A0.z, A0.w, B.x, B.y);
                        }
                    }
                }
            }
        } // p loop

        if (tt + 148 < 512) {
            const float* src = br0 + (size_t)((tt + 148) * 8 + lmt) * 1024
                             + lr * 64 + lq * 16;
#pragma unroll
            for (int j = 0; j < 4; j++) v[j] = *(const float4*)(src + j * 4);
        }

        // ---- epilogue: warp owns M16 rows (mtile mg) x N64 (half ng) ----
        float LA[4] = {0.f, 0.f, 0.f, 0.f}, LB[4] = {0.f, 0.f, 0.f, 0.f};
        const float* Hsf = (const float*)(sm + OFF_HS);
        const float* W2s = (const float*)(sm + OFF_W2);
#pragma unroll
        for (int nb = 0; nb < 8; nb++) {
            int n0 = (ng * 8 + nb) * 8 + tig * 2;
            float4 wa = *(const float4*)&W2s[n0 * 4];
            float4 wb = *(const float4*)&W2s[n0 * 4 + 4];
            float2 hcA = *(const float2*)&Hsf[(mg * 16 + gid) % 8 == (mg * 16 + gid) % 8 ?
                                              ((mg * 2 + 0) * 0 + 0) : 0];
            // (placeholder removed below – real loads:)
            (void)hcA;
            {
                // rows: m = mg*16 + gid  (bl = (mg*16+gid)>>4 ... careful: mg is mtile)
                // Hs layout: [8 bl][128 cols]; row m = mg (bl) ... mtile mg == bl index,
                // fragment row gid maps to head gid and gid+8.
                float2 h0 = *(const float2*)&Hsf[mg * 0 + 0];
                (void)h0;
            }
            // real computation:
            {
                float2 hc = *(const float2*)&Hsf[mg * 128 + n0];
                float h00 = gelu_f(d[nb][0] + hc.x), h01 = gelu_f(d[nb][1] + hc.y);
                float h10 = gelu_f(d[nb][2] + hc.x), h11 = gelu_f(d[nb][3] + hc.y);
                LA[0] += h00 * wa.x + h01 * wb.x; LA[1] += h00 * wa.y + h01 * wb.y;
                LA[2] += h00 * wa.z + h01 * wb.z; LA[3] += h00 * wa.w + h01 * wb.w;
                LB[0] += h10 * wa.x + h11 * wb.x; LB[1] += h10 * wa.y + h11 * wb.y;
                LB[2] += h10 * wa.z + h11 * wb.z; LB[3] += h10 * wa.w + h11 * wb.w;
            }
        }
#pragma unroll
        for (int off = 1; off <= 2; off <<= 1) {
#pragma unroll
            for (int q = 0; q < 4; q++) {
                LA[q] += __shfl_xor_sync(0xffffffffu, LA[q], off);
                LB[q] += __shfl_xor_sync(0xffffffffu, LB[q], off);
            }
        }
        if (tig == 0) {
            float4* Ls = (float4*)(sm + OFF_LS);
            Ls[ng * 128 + mg * 16 + gid]     = make_float4(LA[0], LA[1], LA[2], LA[3]);
            Ls[ng * 128 + mg * 16 + gid + 8] = make_float4(LB[0], LB[1], LB[2], LB[3]);
        }
        __syncthreads();
        if (tid < 128) {
            const float4* Ls = (const float4*)(sm + OFF_LS);
            float4 pa = Ls[tid], pb = Ls[128 + tid];
            float l0 = pa.x + pb.x + b2v.x, l1 = pa.y + pb.y + b2v.y;
            float l2 = pa.z + pb.z + b2v.z, l3 = pa.w + pb.w + b2v.w;
            float s0 = l0 * it_h, s1 = l1 * it_h, s2 = l2 * it_h, s3 = l3 * it_h;
            float m = fmaxf(fmaxf(s0, s1), fmaxf(s2, s3));
            float e0 = expf(s0 - m), e1 = expf(s1 - m);
            float e2 = expf(s2 - m), e3 = expf(s3 - m);
            float inv = 1.f / (e0 + e1 + e2 + e3);
            float w0 = fmaxf(e0 * inv, fl_h.x);
            float w1 = fmaxf(e1 * inv, fl_h.y);
            float w2_ = fmaxf(e2 * inv, fl_h.z);
            float w3 = fmaxf(e3 * inv, fl_h.w);
            float inv2 = 1.f / (w0 + w1 + w2_ + w3);
            int bl = tid >> 4, head = tid & 15;
            *(float4*)(out + (size_t)(base + bl) * 64 + head * 4) =
                make_float4(w0 * inv2, w1 * inv2, w2_ * inv2, w3 * inv2);
        }
        __syncthreads();
    }
}

// ---------------------------------------------------------------------------
extern "C" void kernel_launch(void* const* d_in, const int* in_sizes, int n_in,
                              void* d_out, int out_size) {
    (void)in_sizes; (void)n_in; (void)out_size;
    const float* hidden = (const float*)d_in[0];
    const float* b0     = (const float*)d_in[1];
    const float* b1br   = (const float*)d_in[2];
    const float* b2br   = (const float*)d_in[3];
    const float* b3br   = (const float*)d_in[4];
    const float* W1     = (const float*)d_in[5];
    const float* b1     = (const float*)d_in[6];
    const float* W2     = (const float*)d_in[7];
    const float* b2     = (const float*)d_in[8];
    const float* eps    = (const float*)d_in[9];
    const float* temp   = (const float*)d_in[10];
    float* out = (float*)d_out;

    cudaFuncSetAttribute(prep_mma, cudaFuncAttributeMaxDynamicSharedMemorySize,
                         (int)PREP_SMEM);
    cudaFuncSetAttribute(gate_mma, cudaFuncAttributeMaxDynamicSharedMemorySize,
                         (int)SM_TOT);

    prep_mma<<<173, 256, PREP_SMEM>>>(hidden, W1, b1);
    gate_mma<<<148, 512, SM_TOT>>>(b0, b1br, b2br, b3br, W2, b2, eps, temp, out);
}

// round 10
// speedup vs baseline: 5.9206x; 1.0397x over previous
#include <cuda_runtime.h>
#include <math.h>
#include <stdint.h>

#define NBL  4096
#define HIDD 1024
#define OUTC 128
typedef unsigned long long ull;
typedef uint32_t u32;

// ---------------- device scratch (allocation-free rule) ----------------
__device__ __align__(16) float g_Hc[NBL * OUTC];   // hidden @ W1[0:1024] + b1
__device__ __align__(16) float g_Wt[34816];        // W fragments, paired-nb layout

// ---------------- helpers ----------------
__device__ __forceinline__ float gelu_f(float x) {
    return 0.5f * x * (1.0f + erff(x * 0.70710678118654752440f));
}
__device__ __forceinline__ u32 to_tf32(float x) {
    u32 o;
    asm("cvt.rna.tf32.f32 %0, %1;" : "=r"(o) : "f"(x));
    return o;
}
__device__ __forceinline__ void mma8(float& d0, float& d1, float& d2, float& d3,
                                     u32 a0, u32 a1, u32 a2, u32 a3,
                                     u32 b0, u32 b1) {
    asm volatile("mma.sync.aligned.m16n8k8.row.col.f32.tf32.tf32.f32 "
                 "{%0,%1,%2,%3}, {%4,%5,%6,%7}, {%8,%9}, {%0,%1,%2,%3};"
                 : "+f"(d0), "+f"(d1), "+f"(d2), "+f"(d3)
                 : "r"(a0), "r"(a1), "r"(a2), "r"(a3), "r"(b0), "r"(b1));
}

// ---------------------------------------------------------------------------
// prep_mma:
//  blocks 0..127   : g_Hc = hidden @ W1[0:1024] + b1 (tf32 mma, M=32 tile)
//  blocks 128..159 : branch W fragments (kb = bid-128), paired-nb layout:
//      value (kabs=kb*8+kl, n): word = (kb*8 + (n>>4))*128
//                                    + ((n&7)*4 + (kl&3))*4 + ((n>>3)&1)*2 + (kl>>2)
//  blocks 160..171 : stat-row s = bid-160 fragment (parallel column sums)
//  block  172      : zero-pad fragments for sk 12..15
// ---------------------------------------------------------------------------
#define PREP_SMEM (20480 * 4)

__global__ __launch_bounds__(256) void prep_mma(const float* __restrict__ A,
                                                const float* __restrict__ W1,
                                                const float* __restrict__ b1) {
    const int tid = threadIdx.x;

    if (blockIdx.x >= 128) {
        u32* dst = (u32*)g_Wt;
        if (blockIdx.x < 160) {
            int kb = blockIdx.x - 128;        // 0..31
#pragma unroll
            for (int i = 0; i < 4; i++) {
                int gi = tid + i * 256;       // 0..1023
                int kl = gi >> 7, n = gi & 127;
                float v = W1[(size_t)(1792 + kb * 8 + kl) * 128 + n];
                dst[(u32)((kb * 8 + (n >> 4)) * 128
                    + ((n & 7) * 4 + (kl & 3)) * 4 + ((n >> 3) & 1) * 2 + (kl >> 2))]
                    = to_tf32(v);
            }
        } else if (blockIdx.x < 172) {
            int s = blockIdx.x - 160;         // 0..11
            int n = tid >> 1, half = tid & 1;
            const float* p = W1 + (size_t)(1024 + s * 64 + half * 32) * 128 + n;
            float acc = 0.f;
#pragma unroll 8
            for (int r = 0; r < 32; r++) acc += p[(size_t)r * 128];
            acc += __shfl_xor_sync(0xffffffffu, acc, 1);
            if (!half) {
                int kb = 32 + (s >> 3), kl = s & 7;
                dst[(u32)((kb * 8 + (n >> 4)) * 128
                    + ((n & 7) * 4 + (kl & 3)) * 4 + ((n >> 3) & 1) * 2 + (kl >> 2))]
                    = to_tf32(acc);
            }
        } else {
#pragma unroll
            for (int i = 0; i < 2; i++) {
                int idx = tid + i * 256;      // 0..511
                int sk = 12 + (idx >> 7), n = idx & 127;
                int kl = sk & 7;              // 4..7
                dst[(u32)((33 * 8 + (n >> 4)) * 128
                    + ((n & 7) * 4 + (kl & 3)) * 4 + ((n >> 3) & 1) * 2 + 1)] = 0u;
            }
        }
        return;
    }

    // ---- GEMM part (unchanged from R8 pass) ----
    extern __shared__ u32 smw[];
    u32* Af = smw;
    u32* Bf = smw + 4096;

    const int m0 = blockIdx.x * 32;
    const int lane = tid & 31, warp = tid >> 5;
    const int mg = warp & 1, ng = warp >> 1;

    const int ar = tid >> 3, akb = tid & 7;
    const int arl = ar & 7, arh = ((ar & 15) >= 8) ? 1 : 0;
    const int afrag = akb * 2 + (ar >> 4);
    const u32 aswz = (u32)((arl << 2) ^ (akb << 2));
    const float* Ag = A + (size_t)(m0 + ar) * HIDD + akb * 8;

    const int bk = tid >> 2, bn0 = (tid & 3) * 32;
    const int bkb = bk >> 3, bkl = bk & 7;
    const int bw = (bkl >= 4) ? 1 : 0, bkq = bkl & 3;
    const float* Bg = W1 + (size_t)bk * OUTC + bn0;

    const u32 ard = (u32)((lane * 4) ^ ((lane >> 2) << 2));

    float d[4][4];
#pragma unroll
    for (int i = 0; i < 4; i++)
#pragma unroll
        for (int j = 0; j < 4; j++) d[i][j] = 0.f;

    float av[8];
    float bv[32];

#define LDGA(CK) do {                                                  \
    float4 t0 = *(const float4*)(Ag + (CK) * 64);                      \
    float4 t1 = *(const float4*)(Ag + (CK) * 64 + 4);                  \
    av[0]=t0.x; av[1]=t0.y; av[2]=t0.z; av[3]=t0.w;                    \
    av[4]=t1.x; av[5]=t1.y; av[6]=t1.z; av[7]=t1.w;                    \
} while (0)

#define LDGB(CK) do {                                                  \
    _Pragma("unroll")                                                  \
    for (int g_ = 0; g_ < 8; g_++) {                                   \
        float4 t_ = *(const float4*)(Bg + (size_t)(CK) * 64 * OUTC + g_ * 4); \
        bv[g_*4+0]=t_.x; bv[g_*4+1]=t_.y; bv[g_*4+2]=t_.z; bv[g_*4+3]=t_.w;  \
    }                                                                  \
} while (0)

#define STORE(BUF) do {                                                \
    _Pragma("unroll")                                                  \
    for (int j_ = 0; j_ < 8; j_++) {                                   \
        u32 wi_ = (u32)(arl * 16 + (j_ & 3) * 4 + arh + ((j_ >= 4) ? 2 : 0)) ^ aswz; \
        Af[(BUF) * 2048 + afrag * 128 + wi_] = to_tf32(av[j_]);        \
    }                                                                  \
    _Pragma("unroll")                                                  \
    for (int j_ = 0; j_ < 32; j_++) {                                  \
        int n_ = bn0 + j_;                                             \
        int nb_ = n_ >> 3;                                             \
        u32 x_ = (u32)((((n_ & 7) * 4 + bkq) * 2 + bw)) ^ (u32)(nb_ << 1); \
        Bf[(BUF) * 8192 + (bkb * 16 + nb_) * 64 + x_] = to_tf32(bv[j_]); \
    }                                                                  \
} while (0)

#define MMACHUNK(BUF) do {                                             \
    _Pragma("unroll")                                                  \
    for (int kb_ = 0; kb_ < 8; kb_++) {                                \
        uint4 Av_ = *(const uint4*)&Af[(BUF) * 2048 + (kb_ * 2 + mg) * 128 \
                                       + (ard ^ (u32)(kb_ << 2))];     \
        _Pragma("unroll")                                              \
        for (int q_ = 0; q_ < 4; q_++) {                               \
            int nb_ = ng * 4 + q_;                                     \
            uint2 Bv_ = *(const uint2*)&Bf[(BUF) * 8192 + (kb_ * 16 + nb_) * 64 \
                                           + (u32)((lane * 2) ^ (nb_ << 1))];   \
            mma8(d[q_][0], d[q_][1], d[q_][2], d[q_][3],               \
                 Av_.x, Av_.y, Av_.z, Av_.w, Bv_.x, Bv_.y);            \
        }                                                              \
    }                                                                  \
} while (0)

    LDGA(0); LDGB(0);
    STORE(0);
    __syncthreads();

#pragma unroll 1
    for (int ck = 0; ck < 16; ck++) {
        if (ck < 15) { LDGA(ck + 1); LDGB(ck + 1); }
        MMACHUNK(ck & 1);
        if (ck < 15) {
            __syncthreads();
            STORE((ck + 1) & 1);
            __syncthreads();
        }
    }

    const int row0 = m0 + mg * 16 + (lane >> 2);
    const int col0 = ng * 32 + (lane & 3) * 2;
#pragma unroll
    for (int q = 0; q < 4; q++) {
        int col = col0 + q * 8;
        float2 bb = *(const float2*)(b1 + col);
        *(float2*)&g_Hc[(size_t)row0 * OUTC + col] =
            make_float2(d[q][0] + bb.x, d[q][1] + bb.y);
        *(float2*)&g_Hc[(size_t)(row0 + 8) * OUTC + col] =
            make_float2(d[q][2] + bb.x, d[q][3] + bb.y);
    }
}

// ---------------------------------------------------------------------------
// gate_mma: persistent tf32 mma gate kernel. 512 threads (16 warps).
// Tile M=128 (8 bl x 16 heads), N=128, K=272.
// Warp (mp=warp>>2 -> mtiles 2mp,2mp+1; nq=warp&3 -> nb 4nq..4nq+3): M32 x N32.
// W in paired-nb fragment layout -> one conflict-free LDS.128 per (kb, np).
// ---------------------------------------------------------------------------
#define OFF_W  0u        // 139264 : W fragments
#define OFF_X  139264u   // 2 x 32768 : X branch fragments (double buffer)
#define OFF_XS 204800u   // 8192 : X stats fragments
#define OFF_HS 212992u   // 4096 : g_Hc staging
#define OFF_LS 217088u   // 8192 : logit exchange [4][128][4]
#define OFF_W2 225280u   // 2048 : W2
#define SM_TOT 227328u

__global__ __launch_bounds__(512, 1) void gate_mma(
    const float* __restrict__ br0, const float* __restrict__ br1,
    const float* __restrict__ br2, const float* __restrict__ br3,
    const float* __restrict__ W2,  const float* __restrict__ b2,
    const float* __restrict__ eps, const float* __restrict__ temp,
    float* __restrict__ out)
{
    extern __shared__ char sm[];
    const int tid  = threadIdx.x;
    const int lane = tid & 31, warp = tid >> 5;
    const int mp = warp >> 2, nq = warp & 3;

    {
        const float4* s = (const float4*)g_Wt;
        float4* d = (float4*)(sm + OFF_W);
        for (int i = tid; i < 8704; i += 512) d[i] = s[i];
    }
    {
        float4* d = (float4*)(sm + OFF_XS);
        for (int i = tid; i < 512; i += 512) d[i] = make_float4(0.f, 0.f, 0.f, 0.f);
    }
    {
        float* d = (float*)(sm + OFF_W2);
        d[tid] = W2[tid & 511];
    }
    const float4 b2v = *(const float4*)b2;
    float it_h = 1.f;
    float4 fl_h = make_float4(0.f, 0.f, 0.f, 0.f);
    if (tid < 128) {
        int head = tid & 15;
        it_h = 1.f / fminf(fmaxf(temp[head], 0.2f), 10.0f);
        float4 ef = *(const float4*)(eps + head * 4);
        fl_h.x = fminf(fmaxf(ef.x, 1e-7f), 0.1f);
        fl_h.y = fminf(fmaxf(ef.y, 1e-7f), 0.1f);
        fl_h.z = fminf(fmaxf(ef.z, 1e-7f), 0.1f);
        fl_h.w = fminf(fmaxf(ef.w, 1e-7f), 0.1f);
    }
    __syncthreads();

    // loader: thread t -> row lm = t>>2, quarter lq = t&3 (16 k-values)
    const int lm = tid >> 2, lq = tid & 3;
    const int lmt = lm >> 4;
    const int lr  = lm & 15;
    const int rlow = lr & 7, rhi = (lr >= 8) ? 1 : 0;
    const int swzr = rlow << 2;
    const int swz_l = (lane * 4) ^ ((lane >> 2) << 2);
    const int tig = lane & 3, gid = lane >> 2;

    float4 v[4];
    int tt = blockIdx.x;
    {
        const float* src = br0 + (size_t)(tt * 8 + lmt) * 1024 + lr * 64 + lq * 16;
#pragma unroll
        for (int j = 0; j < 4; j++) v[j] = *(const float4*)(src + j * 4);
    }

    for (; tt < 512; tt += 148) {
        const int base = tt * 8;

        if (tid < 256) {
            const float4* s = (const float4*)(g_Hc + (size_t)base * 128);
            ((float4*)(sm + OFF_HS))[tid] = s[tid];
        }

        float dd[2][4][4];
#pragma unroll
        for (int mt = 0; mt < 2; mt++)
#pragma unroll
            for (int nb = 0; nb < 4; nb++)
#pragma unroll
                for (int c = 0; c < 4; c++) dd[mt][nb][c] = 0.f;

#pragma unroll 1
        for (int p = 0; p < 4; p++) {
            float s = 0.f, q2 = 0.f, mx = -INFINITY;
#pragma unroll
            for (int j = 0; j < 4; j++) {
                s  += (v[j].x + v[j].y) + (v[j].z + v[j].w);
                q2 += v[j].x * v[j].x + v[j].y * v[j].y
                    + v[j].z * v[j].z + v[j].w * v[j].w;
                mx = fmaxf(mx, fmaxf(fmaxf(v[j].x, v[j].y), fmaxf(v[j].z, v[j].w)));
            }
            s  += __shfl_xor_sync(0xffffffffu, s, 1);
            q2 += __shfl_xor_sync(0xffffffffu, q2, 1);
            mx  = fmaxf(mx, __shfl_xor_sync(0xffffffffu, mx, 1));
            s  += __shfl_xor_sync(0xffffffffu, s, 2);
            q2 += __shfl_xor_sync(0xffffffffu, q2, 2);
            mx  = fmaxf(mx, __shfl_xor_sync(0xffffffffu, mx, 2));

            {
                u32* xb = (u32*)(sm + OFF_X) + (p & 1) * 8192 + lmt * 1024;
                const float* vf = (const float*)v;
#pragma unroll
                for (int j = 0; j < 16; j++) {
                    int kbl = lq * 2 + (j >> 3);
                    int kp  = j & 7;
                    int off = (rlow * 16 + (kp & 3) * 4 + rhi + ((kp >= 4) ? 2 : 0)) ^ swzr;
                    xb[kbl * 128 + off] = to_tf32(vf[j]);
                }
                if (lq == 0) {
                    float st0 = s * (1.f / 64.f);
                    float st1 = sqrtf(fmaxf(q2 * (1.f / 64.f), 1e-8f));
                    float st2 = mx;
                    u32* xs = (u32*)(sm + OFF_XS) + lmt * 256;
#pragma unroll
                    for (int t2 = 0; t2 < 3; t2++) {
                        int sk = p * 3 + t2;
                        int kbs = sk >> 3, kp = sk & 7;
                        int off = (rlow * 16 + (kp & 3) * 4 + rhi + ((kp >= 4) ? 2 : 0)) ^ swzr;
                        float sv = (t2 == 0) ? st0 : (t2 == 1) ? st1 : st2;
                        xs[kbs * 128 + off] = to_tf32(sv);
                    }
                }
            }
            __syncthreads();

            if (p < 3) {
                const float* bp = (p == 0) ? br1 : (p == 1) ? br2 : br3;
                const float* src = bp + (size_t)(base + lmt) * 1024 + lr * 64 + lq * 16;
#pragma unroll
                for (int j = 0; j < 4; j++) v[j] = *(const float4*)(src + j * 4);
            }

            {
                const char* xbase = sm + OFF_X + (p & 1) * 32768u;
                const char* ab = xbase + (u32)(2 * mp) * 4096u + (u32)swz_l * 4u;
#pragma unroll 2
                for (int kbl = 0; kbl < 8; kbl++) {
                    const char* wk = sm + OFF_W
                                   + (u32)(((p * 8 + kbl) * 8 + 2 * nq) * 512)
                                   + (u32)lane * 16u;
                    uint4 B0 = *(const uint4*)(wk);
                    uint4 B1 = *(const uint4*)(wk + 512);
                    uint4 A0 = *(const uint4*)(ab + kbl * 512);
                    mma8(dd[0][0][0], dd[0][0][1], dd[0][0][2], dd[0][0][3],
                         A0.x, A0.y, A0.z, A0.w, B0.x, B0.y);
                    mma8(dd[0][1][0], dd[0][1][1], dd[0][1][2], dd[0][1][3],
                         A0.x, A0.y, A0.z, A0.w, B0.z, B0.w);
                    mma8(dd[0][2][0], dd[0][2][1], dd[0][2][2], dd[0][2][3],
                         A0.x, A0.y, A0.z, A0.w, B1.x, B1.y);
                    mma8(dd[0][3][0], dd[0][3][1], dd[0][3][2], dd[0][3][3],
                         A0.x, A0.y, A0.z, A0.w, B1.z, B1.w);
                    uint4 A1 = *(const uint4*)(ab + 4096 + kbl * 512);
                    mma8(dd[1][0][0], dd[1][0][1], dd[1][0][2], dd[1][0][3],
                         A1.x, A1.y, A1.z, A1.w, B0.x, B0.y);
                    mma8(dd[1][1][0], dd[1][1][1], dd[1][1][2], dd[1][1][3],
                         A1.x, A1.y, A1.z, A1.w, B0.z, B0.w);
                    mma8(dd[1][2][0], dd[1][2][1], dd[1][2][2], dd[1][2][3],
                         A1.x, A1.y, A1.z, A1.w, B1.x, B1.y);
                    mma8(dd[1][3][0], dd[1][3][1], dd[1][3][2], dd[1][3][3],
                         A1.x, A1.y, A1.z, A1.w, B1.z, B1.w);
                }
                if (p == 3) {
                    const char* sb = sm + OFF_XS + (u32)(2 * mp) * 1024u
                                   + (u32)swz_l * 4u;
#pragma unroll
                    for (int kbs = 0; kbs < 2; kbs++) {
                        const char* wk = sm + OFF_W
                                       + (u32)((((32 + kbs) * 8) + 2 * nq) * 512)
                                       + (u32)lane * 16u;
                        uint4 B0 = *(const uint4*)(wk);
                        uint4 B1 = *(const uint4*)(wk + 512);
                        uint4 A0 = *(const uint4*)(sb + kbs * 512);
                        mma8(dd[0][0][0], dd[0][0][1], dd[0][0][2], dd[0][0][3],
                             A0.x, A0.y, A0.z, A0.w, B0.x, B0.y);
                        mma8(dd[0][1][0], dd[0][1][1], dd[0][1][2], dd[0][1][3],
                             A0.x, A0.y, A0.z, A0.w, B0.z, B0.w);
                        mma8(dd[0][2][0], dd[0][2][1], dd[0][2][2], dd[0][2][3],
                             A0.x, A0.y, A0.z, A0.w, B1.x, B1.y);
                        mma8(dd[0][3][0], dd[0][3][1], dd[0][3][2], dd[0][3][3],
                             A0.x, A0.y, A0.z, A0.w, B1.z, B1.w);
                        uint4 A1 = *(const uint4*)(sb + 1024 + kbs * 512);
                        mma8(dd[1][0][0], dd[1][0][1], dd[1][0][2], dd[1][0][3],
                             A1.x, A1.y, A1.z, A1.w, B0.x, B0.y);
                        mma8(dd[1][1][0], dd[1][1][1], dd[1][1][2], dd[1][1][3],
                             A1.x, A1.y, A1.z, A1.w, B0.z, B0.w);
                        mma8(dd[1][2][0], dd[1][2][1], dd[1][2][2], dd[1][2][3],
                             A1.x, A1.y, A1.z, A1.w, B1.x, B1.y);
                        mma8(dd[1][3][0], dd[1][3][1], dd[1][3][2], dd[1][3][3],
                             A1.x, A1.y, A1.z, A1.w, B1.z, B1.w);
                    }
                }
            }
        } // p loop

        if (tt + 148 < 512) {
            const float* src = br0 + (size_t)((tt + 148) * 8 + lmt) * 1024
                             + lr * 64 + lq * 16;
#pragma unroll
            for (int j = 0; j < 4; j++) v[j] = *(const float4*)(src + j * 4);
        }

        // ---- epilogue: warp owns mtiles 2mp,2mp+1 x N32 (nq) ----
        const float* Hsf = (const float*)(sm + OFF_HS);
        const float* W2s = (const float*)(sm + OFF_W2);
#pragma unroll
        for (int mt = 0; mt < 2; mt++) {
            float LA[4] = {0.f, 0.f, 0.f, 0.f}, LB[4] = {0.f, 0.f, 0.f, 0.f};
            const float* hrow = Hsf + (2 * mp + mt) * 128;
#pragma unroll
            for (int nbl = 0; nbl < 4; nbl++) {
                int n0 = (nq * 4 + nbl) * 8 + tig * 2;
                float4 wa = *(const float4*)&W2s[n0 * 4];
                float4 wb = *(const float4*)&W2s[n0 * 4 + 4];
                float2 hc = *(const float2*)&hrow[n0];
                float h00 = gelu_f(dd[mt][nbl][0] + hc.x);
                float h01 = gelu_f(dd[mt][nbl][1] + hc.y);
                float h10 = gelu_f(dd[mt][nbl][2] + hc.x);
                float h11 = gelu_f(dd[mt][nbl][3] + hc.y);
                LA[0] += h00 * wa.x + h01 * wb.x; LA[1] += h00 * wa.y + h01 * wb.y;
                LA[2] += h00 * wa.z + h01 * wb.z; LA[3] += h00 * wa.w + h01 * wb.w;
                LB[0] += h10 * wa.x + h11 * wb.x; LB[1] += h10 * wa.y + h11 * wb.y;
                LB[2] += h10 * wa.z + h11 * wb.z; LB[3] += h10 * wa.w + h11 * wb.w;
            }
#pragma unroll
            for (int off = 1; off <= 2; off <<= 1) {
#pragma unroll
                for (int q = 0; q < 4; q++) {
                    LA[q] += __shfl_xor_sync(0xffffffffu, LA[q], off);
                    LB[q] += __shfl_xor_sync(0xffffffffu, LB[q], off);
                }
            }
            if (tig == 0) {
                float4* Ls = (float4*)(sm + OFF_LS);
                int r = (2 * mp + mt) * 16 + gid;
                Ls[nq * 128 + r]     = make_float4(LA[0], LA[1], LA[2], LA[3]);
                Ls[nq * 128 + r + 8] = make_float4(LB[0], LB[1], LB[2], LB[3]);
            }
        }
        __syncthreads();
        if (tid < 128) {
            const float4* Ls = (const float4*)(sm + OFF_LS);
            float4 p0 = Ls[tid], p1 = Ls[128 + tid];
            float4 p2 = Ls[256 + tid], p3 = Ls[384 + tid];
            float l0 = p0.x + p1.x + p2.x + p3.x + b2v.x;
            float l1 = p0.y + p1.y + p2.y + p3.y + b2v.y;
            float l2 = p0.z + p1.z + p2.z + p3.z + b2v.z;
            float l3 = p0.w + p1.w + p2.w + p3.w + b2v.w;
            float s0 = l0 * it_h, s1 = l1 * it_h, s2 = l2 * it_h, s3 = l3 * it_h;
            float m = fmaxf(fmaxf(s0, s1), fmaxf(s2, s3));
            float e0 = expf(s0 - m), e1 = expf(s1 - m);
            float e2 = expf(s2 - m), e3 = expf(s3 - m);
            float inv = 1.f / (e0 + e1 + e2 + e3);
            float w0 = fmaxf(e0 * inv, fl_h.x);
            float w1 = fmaxf(e1 * inv, fl_h.y);
            float w2_ = fmaxf(e2 * inv, fl_h.z);
            float w3 = fmaxf(e3 * inv, fl_h.w);
            float inv2 = 1.f / (w0 + w1 + w2_ + w3);
            int bl = tid >> 4, head = tid & 15;
            *(float4*)(out + (size_t)(base + bl) * 64 + head * 4) =
                make_float4(w0 * inv2, w1 * inv2, w2_ * inv2, w3 * inv2);
        }
        __syncthreads();
    }
}

// ---------------------------------------------------------------------------
extern "C" void kernel_launch(void* const* d_in, const int* in_sizes, int n_in,
                              void* d_out, int out_size) {
    (void)in_sizes; (void)n_in; (void)out_size;
    const float* hidden = (const float*)d_in[0];
    const float* b0     = (const float*)d_in[1];
    const float* b1br   = (const float*)d_in[2];
    const float* b2br   = (const float*)d_in[3];
    const float* b3br   = (const float*)d_in[4];
    const float* W1     = (const float*)d_in[5];
    const float* b1     = (const float*)d_in[6];
    const float* W2     = (const float*)d_in[7];
    const float* b2     = (const float*)d_in[8];
    const float* eps    = (const float*)d_in[9];
    const float* temp   = (const float*)d_in[10];
    float* out = (float*)d_out;

    cudaFuncSetAttribute(prep_mma, cudaFuncAttributeMaxDynamicSharedMemorySize,
                         (int)PREP_SMEM);
    cudaFuncSetAttribute(gate_mma, cudaFuncAttributeMaxDynamicSharedMemorySize,
                         (int)SM_TOT);

    prep_mma<<<173, 256, PREP_SMEM>>>(hidden, W1, b1);
    gate_mma<<<148, 512, SM_TOT>>>(b0, b1br, b2br, b3br, W2, b2, eps, temp, out);
}